// round 4
// baseline (speedup 1.0000x reference)
#include <cuda_runtime.h>
#include <mma.h>
#include <math.h>
using namespace nvcuda;

// Problem constants
#define BB   32
#define SS   100
#define DD   256
#define HH   4
#define DK_  64
#define LL   3
#define MM   (BB*SS)      // 3200
#define DFF_ 1024
#define NOUT 50001

// ---------------- scratch (no allocation allowed -> device globals) ----------------
__device__ float g_h[MM*DD];
__device__ float g_temb[MM*DD];
__device__ float g_hn[MM*DD];
__device__ float g_q[MM*DD];
__device__ float g_k1[MM*DD];
__device__ float g_k2[MM*DD];
__device__ float g_v[MM*DD];
__device__ float g_ctx[MM*DD];
__device__ float g_ffn[MM*DFF_];

// ---------------- embedding + time embedding ----------------
__global__ void embed_kernel(const int* __restrict__ x, const float* __restrict__ times,
                             const float* __restrict__ token_emb, const float* __restrict__ pos_emb,
                             const float* __restrict__ sel_w, const float* __restrict__ sel_b,
                             const float* __restrict__ time_w, const float* __restrict__ time_b,
                             const float* __restrict__ per_w, const float* __restrict__ per_b)
{
    int bs = blockIdx.x;           // 0..3199
    int s  = bs % SS;
    int d  = threadIdx.x;          // 0..255
    __shared__ float g[64];
    float tval = times[bs];
    if (d < 64) {
        float t = tval * (1.0f/180.0f) * sel_w[d] + sel_b[d];
        g[d] = 1.0f - tanhf(t*t);
    }
    __syncthreads();
    float ang = 2.0f * 3.14159265358979323846f * tval / 24.0f;
    float sa = sinf(ang), ca = cosf(ang);
    float feat = time_b[d];
    const float* tw = time_w + d*64;
    #pragma unroll 16
    for (int j = 0; j < 64; j++) feat += g[j] * tw[j];
    float per = sa*per_w[d*2+0] + ca*per_w[d*2+1] + per_b[d];
    g_temb[bs*DD + d] = feat + per;
    int tok = x[bs];
    g_h[bs*DD + d] = token_emb[(size_t)tok*DD + d] + pos_emb[s*DD + d];
}

// ---------------- LayerNorm (torch variant: unbiased std, eps added to std) ----------------
__global__ void ln_kernel(const float* __restrict__ x, const float* __restrict__ a,
                          const float* __restrict__ b, float* __restrict__ y)
{
    int row = blockIdx.x;
    int d = threadIdx.x;
    int lane = d & 31, warp = d >> 5;
    __shared__ float ws1[8], ws2[8];
    float v = x[row*DD + d];
    float s = v;
    #pragma unroll
    for (int o = 16; o > 0; o >>= 1) s += __shfl_xor_sync(0xffffffff, s, o);
    if (lane == 0) ws1[warp] = s;
    __syncthreads();
    float tot = 0.f;
    #pragma unroll
    for (int i = 0; i < 8; i++) tot += ws1[i];
    float mean = tot * (1.0f/DD);
    float diff = v - mean;
    float s2 = diff*diff;
    #pragma unroll
    for (int o = 16; o > 0; o >>= 1) s2 += __shfl_xor_sync(0xffffffff, s2, o);
    if (lane == 0) ws2[warp] = s2;
    __syncthreads();
    float tot2 = 0.f;
    #pragma unroll
    for (int i = 0; i < 8; i++) tot2 += ws2[i];
    float stdv = sqrtf(tot2 * (1.0f/(DD-1)));
    y[row*DD + d] = a[d]*diff/(stdv + 1e-6f) + b[d];
}

// ---------------- GELU ----------------
__device__ __forceinline__ float gelu_f(float x) {
    const float c = 0.7978845608028654f;   // sqrt(2/pi)
    float x3 = x*x*x;
    return 0.5f*x*(1.0f + tanhf(c*(x + 0.044715f*x3)));
}

__device__ __forceinline__ float4 tf4(float4 a) {
    return make_float4(wmma::__float_to_tf32(a.x), wmma::__float_to_tf32(a.y),
                       wmma::__float_to_tf32(a.z), wmma::__float_to_tf32(a.w));
}

// ---------------- TF32 WMMA GEMM v1: 128x128 tile, warp 64x32, BK=16, double buffered ----------------
#define BKT  16
#define LDS_ 20

__device__ __forceinline__ void gemm_body(const float* __restrict__ A,
                                          const float* __restrict__ W,
                                          const float* __restrict__ bias,
                                          const float* __restrict__ res,
                                          float* __restrict__ C,
                                          int N, int K, int row0, int col0, int epi)
{
    __shared__ float As[2][128*LDS_];
    __shared__ float Ws[2][128*LDS_];
    __shared__ float stage[8][16*16];

    int tid  = threadIdx.x;
    int warp = tid >> 5;
    int lane = tid & 31;
    int wm = warp & 1;
    int wn = warp >> 1;

    wmma::fragment<wmma::accumulator,16,16,8,float> acc[4][2];
    #pragma unroll
    for (int i = 0; i < 4; i++)
        #pragma unroll
        for (int j = 0; j < 2; j++) wmma::fill_fragment(acc[i][j], 0.0f);

    int lrow = tid >> 1;
    int lcol = (tid & 1) * 8;
    const float* Ag = A + (size_t)(row0 + lrow)*K + lcol;
    int wrow = col0 + lrow;
    const float* Wg = W + (size_t)wrow*K + lcol;
    bool wv = wrow < N;

    float* asp0 = &As[0][lrow*LDS_ + lcol];
    float* wsp0 = &Ws[0][lrow*LDS_ + lcol];
    float* asp1 = &As[1][lrow*LDS_ + lcol];
    float* wsp1 = &Ws[1][lrow*LDS_ + lcol];

    {
        float4 a0 = *(const float4*)(Ag);
        float4 a1 = *(const float4*)(Ag + 4);
        float4 w0 = wv ? *(const float4*)(Wg)     : make_float4(0.f,0.f,0.f,0.f);
        float4 w1 = wv ? *(const float4*)(Wg + 4) : make_float4(0.f,0.f,0.f,0.f);
        *(float4*)(asp0)     = tf4(a0); *(float4*)(asp0 + 4) = tf4(a1);
        *(float4*)(wsp0)     = tf4(w0); *(float4*)(wsp0 + 4) = tf4(w1);
    }
    __syncthreads();

    int buf = 0;
    for (int kk = BKT; kk <= K; kk += BKT) {
        float4 na0, na1, nw0, nw1;
        bool more = (kk < K);
        if (more) {
            na0 = *(const float4*)(Ag + kk);
            na1 = *(const float4*)(Ag + kk + 4);
            nw0 = wv ? *(const float4*)(Wg + kk)     : make_float4(0.f,0.f,0.f,0.f);
            nw1 = wv ? *(const float4*)(Wg + kk + 4) : make_float4(0.f,0.f,0.f,0.f);
        }
        const float* Ab = &As[buf][0];
        const float* Wb = &Ws[buf][0];
        #pragma unroll
        for (int ks = 0; ks < BKT; ks += 8) {
            wmma::fragment<wmma::matrix_a,16,16,8,wmma::precision::tf32,wmma::row_major> af[4];
            wmma::fragment<wmma::matrix_b,16,16,8,wmma::precision::tf32,wmma::col_major> bf[2];
            #pragma unroll
            for (int i = 0; i < 4; i++)
                wmma::load_matrix_sync(af[i], Ab + (wm*64 + i*16)*LDS_ + ks, LDS_);
            #pragma unroll
            for (int j = 0; j < 2; j++)
                wmma::load_matrix_sync(bf[j], Wb + (wn*32 + j*16)*LDS_ + ks, LDS_);
            #pragma unroll
            for (int i = 0; i < 4; i++)
                #pragma unroll
                for (int j = 0; j < 2; j++)
                    wmma::mma_sync(acc[i][j], af[i], bf[j], acc[i][j]);
        }
        if (more) {
            float* ad = buf ? asp0 : asp1;
            float* wd = buf ? wsp0 : wsp1;
            *(float4*)(ad)     = tf4(na0); *(float4*)(ad + 4) = tf4(na1);
            *(float4*)(wd)     = tf4(nw0); *(float4*)(wd + 4) = tf4(nw1);
            __syncthreads();
            buf ^= 1;
        }
    }

    float* st = stage[warp];
    int r  = lane >> 1;
    int c0 = (lane & 1) * 8;
    #pragma unroll
    for (int i = 0; i < 4; i++) {
        #pragma unroll
        for (int j = 0; j < 2; j++) {
            wmma::store_matrix_sync(st, acc[i][j], 16, wmma::mem_row_major);
            __syncwarp();
            int grow  = row0 + wm*64 + i*16 + r;
            int gcolb = col0 + wn*32 + j*16 + c0;
            #pragma unroll
            for (int c = 0; c < 8; c++) {
                int gc = gcolb + c;
                if (gc < N) {
                    float v = st[r*16 + c0 + c] + bias[gc];
                    if (epi == 1) v = gelu_f(v);
                    else if (epi == 2) v += res[(size_t)grow*N + gc];
                    C[(size_t)grow*N + gc] = v;
                }
            }
            __syncwarp();
        }
    }
}

__global__ void __launch_bounds__(256) gemm_tf32(const float* __restrict__ A,
                                                 const float* __restrict__ W,
                                                 const float* __restrict__ bias,
                                                 const float* __restrict__ res,
                                                 float* __restrict__ C, int N, int K, int epi)
{
    gemm_body(A, W, bias, res, C, N, K, blockIdx.y*128, blockIdx.x*128, epi);
}

__global__ void __launch_bounds__(256) qktv_gemm(const float* __restrict__ hn,
                                                 const float* __restrict__ temb,
                                                 const float* __restrict__ Wq, const float* __restrict__ Wk,
                                                 const float* __restrict__ Wt, const float* __restrict__ Wv,
                                                 const float* __restrict__ bq, const float* __restrict__ bk,
                                                 const float* __restrict__ bt, const float* __restrict__ bv,
                                                 float* __restrict__ q, float* __restrict__ k1,
                                                 float* __restrict__ k2, float* __restrict__ v)
{
    int z = blockIdx.z;
    const float* A = (z == 2) ? temb : hn;
    const float* W = (z == 0) ? Wq : (z == 1) ? Wk : (z == 2) ? Wt : Wv;
    const float* b = (z == 0) ? bq : (z == 1) ? bk : (z == 2) ? bt : bv;
    float*       C = (z == 0) ? q  : (z == 1) ? k1 : (z == 2) ? k2 : v;
    gemm_body(A, W, b, nullptr, C, DD, DD, blockIdx.y*128, blockIdx.x*128, 0);
}

// ---------------- TF32 WMMA GEMM v2: 128x256 tile, warp 64x64, BK=16, double buffered ----------------
// dynamic smem layout (floats): As[2][128*20] @0, Ws[2][256*20] @5120, stage[8][256] @15360
__global__ void __launch_bounds__(256) gemm2_tf32(const float* __restrict__ A,
                                                  const float* __restrict__ W,
                                                  const float* __restrict__ bias,
                                                  float* __restrict__ C, int N, int K, int epi)
{
    extern __shared__ float sm2[];
    float* AsB = sm2;                // 2 * 2560
    float* WsB = sm2 + 5120;         // 2 * 5120
    float* stg = sm2 + 15360;        // 8 * 256

    int row0 = blockIdx.y * 128, col0 = blockIdx.x * 256;
    int tid  = threadIdx.x;
    int warp = tid >> 5;
    int lane = tid & 31;
    int wm = warp & 1;      // 2 M-halves (64)
    int wn = warp >> 1;     // 4 N-quarters (64)

    wmma::fragment<wmma::accumulator,16,16,8,float> acc[4][4];
    #pragma unroll
    for (int i = 0; i < 4; i++)
        #pragma unroll
        for (int j = 0; j < 4; j++) wmma::fill_fragment(acc[i][j], 0.0f);

    // A: thread -> row tid&127, k-offset (tid>>7)*8 (8 floats)
    int arow = tid & 127;
    int akoff = (tid >> 7) * 8;
    const float* Ag = A + (size_t)(row0 + arow)*K + akoff;
    float* asp0 = AsB + arow*LDS_ + akoff;
    float* asp1 = asp0 + 2560;
    // W: thread -> row tid (16 floats)
    int wrow = col0 + tid;
    const float* Wg = W + (size_t)wrow*K;
    bool wv = wrow < N;
    float* wsp0 = WsB + tid*LDS_;
    float* wsp1 = wsp0 + 5120;

    {
        float4 a0 = *(const float4*)(Ag);
        float4 a1 = *(const float4*)(Ag + 4);
        *(float4*)(asp0)     = tf4(a0); *(float4*)(asp0 + 4) = tf4(a1);
        float4 z4 = make_float4(0.f,0.f,0.f,0.f);
        float4 w0 = wv ? *(const float4*)(Wg)      : z4;
        float4 w1 = wv ? *(const float4*)(Wg + 4)  : z4;
        float4 w2 = wv ? *(const float4*)(Wg + 8)  : z4;
        float4 w3 = wv ? *(const float4*)(Wg + 12) : z4;
        *(float4*)(wsp0)      = tf4(w0); *(float4*)(wsp0 + 4)  = tf4(w1);
        *(float4*)(wsp0 + 8)  = tf4(w2); *(float4*)(wsp0 + 12) = tf4(w3);
    }
    __syncthreads();

    int buf = 0;
    for (int kk = BKT; kk <= K; kk += BKT) {
        float4 na0, na1, nw0, nw1, nw2, nw3;
        bool more = (kk < K);
        if (more) {
            na0 = *(const float4*)(Ag + kk);
            na1 = *(const float4*)(Ag + kk + 4);
            float4 z4 = make_float4(0.f,0.f,0.f,0.f);
            nw0 = wv ? *(const float4*)(Wg + kk)      : z4;
            nw1 = wv ? *(const float4*)(Wg + kk + 4)  : z4;
            nw2 = wv ? *(const float4*)(Wg + kk + 8)  : z4;
            nw3 = wv ? *(const float4*)(Wg + kk + 12) : z4;
        }
        const float* Ab = AsB + buf*2560;
        const float* Wb = WsB + buf*5120;
        #pragma unroll
        for (int ks = 0; ks < BKT; ks += 8) {
            wmma::fragment<wmma::matrix_a,16,16,8,wmma::precision::tf32,wmma::row_major> af[4];
            wmma::fragment<wmma::matrix_b,16,16,8,wmma::precision::tf32,wmma::col_major> bf[4];
            #pragma unroll
            for (int i = 0; i < 4; i++)
                wmma::load_matrix_sync(af[i], Ab + (wm*64 + i*16)*LDS_ + ks, LDS_);
            #pragma unroll
            for (int j = 0; j < 4; j++)
                wmma::load_matrix_sync(bf[j], Wb + (wn*64 + j*16)*LDS_ + ks, LDS_);
            #pragma unroll
            for (int i = 0; i < 4; i++)
                #pragma unroll
                for (int j = 0; j < 4; j++)
                    wmma::mma_sync(acc[i][j], af[i], bf[j], acc[i][j]);
        }
        if (more) {
            float* ad = buf ? asp0 : asp1;
            float* wd = buf ? wsp0 : wsp1;
            *(float4*)(ad)      = tf4(na0); *(float4*)(ad + 4)  = tf4(na1);
            *(float4*)(wd)      = tf4(nw0); *(float4*)(wd + 4)  = tf4(nw1);
            *(float4*)(wd + 8)  = tf4(nw2); *(float4*)(wd + 12) = tf4(nw3);
            __syncthreads();
            buf ^= 1;
        }
    }

    float* st = stg + warp*256;
    int r  = lane >> 1;
    int c0 = (lane & 1) * 8;
    #pragma unroll
    for (int i = 0; i < 4; i++) {
        #pragma unroll
        for (int j = 0; j < 4; j++) {
            wmma::store_matrix_sync(st, acc[i][j], 16, wmma::mem_row_major);
            __syncwarp();
            int grow  = row0 + wm*64 + i*16 + r;
            int gcolb = col0 + wn*64 + j*16 + c0;
            #pragma unroll
            for (int c = 0; c < 8; c++) {
                int gc = gcolb + c;
                if (gc < N) {
                    float v = st[r*16 + c0 + c] + bias[gc];
                    if (epi == 1) v = gelu_f(v);
                    C[(size_t)grow*N + gc] = v;
                }
            }
            __syncwarp();
        }
    }
}

// ---------------- attention: one block per (b,h), 512 threads, combined-K ----------------
#define KTP 104   // padded pitch for transposed K tile

__global__ void __launch_bounds__(512) attn_kernel(
        const float* __restrict__ q, const float* __restrict__ k1,
        const float* __restrict__ k2, const float* __restrict__ v,
        const int* __restrict__ x, const float* __restrict__ ml,
        float* __restrict__ ctx)
{
    extern __shared__ float sm[];
    float* qs  = sm;                     // 100*64
    float* vs  = qs  + SS*DK_;           // 100*64
    float* kct = vs  + SS*DK_;           // 64*104 (transposed, combined)
    float* sc  = kct + DK_*KTP;          // 100*100
    float* offs= sc + SS*SS;             // 100
    int h = blockIdx.x, b = blockIdx.y;
    int tid = threadIdx.x;
    int lane = tid & 31, warp = tid >> 5;
    int base = b*SS*DD + h*DK_;

    for (int idx = tid; idx < SS*DK_; idx += 512) {
        int s = idx >> 6, d = idx & 63;
        int gi = base + s*DD + d;
        qs[idx] = q[gi];
        vs[idx] = v[gi];
        bool kp = x[b*SS + s] > 0;
        float k2v = k2[gi];
        kct[d*KTP + s] = kp ? (k1[gi] + k2v) : k2v;
    }
    if (tid < SS) offs[tid] = (x[b*SS + tid] > 0) ? 0.0f : -1e9f;
    __syncthreads();

    // Phase A: scores = q . kcomb * scale + offs
    const float scale = 0.125f;  // 1/sqrt(64)
    for (int g = tid; g < SS*25; g += 512) {
        int qi = g / 25;
        int kg = (g - qi*25) * 4;
        const float* qp = qs + qi*DK_;
        float4 s1 = make_float4(0.f,0.f,0.f,0.f);
        #pragma unroll 8
        for (int d = 0; d < DK_; d++) {
            float qv = qp[d];
            float4 b1 = *(const float4*)(kct + d*KTP + kg);
            s1.x += qv*b1.x; s1.y += qv*b1.y; s1.z += qv*b1.z; s1.w += qv*b1.w;
        }
        float* sr = sc + qi*SS + kg;
        const float* op = offs + kg;
        sr[0] = s1.x*scale + op[0];
        sr[1] = s1.y*scale + op[1];
        sr[2] = s1.z*scale + op[2];
        sr[3] = s1.w*scale + op[3];
    }
    __syncthreads();

    // Phase B: softmax per row * sigmoid(mask_logits), warp per row
    for (int r = warp; r < SS; r += 16) {
        float* row = sc + r*SS;
        float mx = -1e30f;
        for (int c = lane; c < SS; c += 32) mx = fmaxf(mx, row[c]);
        #pragma unroll
        for (int o = 16; o > 0; o >>= 1) mx = fmaxf(mx, __shfl_xor_sync(0xffffffff, mx, o));
        float sum = 0.f;
        for (int c = lane; c < SS; c += 32) {
            float e = __expf(row[c] - mx);
            row[c] = e; sum += e;
        }
        #pragma unroll
        for (int o = 16; o > 0; o >>= 1) sum += __shfl_xor_sync(0xffffffff, sum, o);
        float inv = 1.0f / sum;
        const float* mlr = ml + r*SS;
        for (int c = lane; c < SS; c += 32) {
            float z = mlr[c];
            float sg = 1.0f / (1.0f + __expf(-z));
            row[c] *= inv * sg;
        }
    }
    __syncthreads();

    // Phase C: ctx = p @ V
    for (int o = tid; o < SS*16; o += 512) {
        int qi = o >> 4;
        int dg = (o & 15) * 4;
        const float* sr = sc + qi*SS;
        const float* vp = vs + dg;
        float4 a = make_float4(0.f,0.f,0.f,0.f);
        #pragma unroll 4
        for (int k = 0; k < SS; k++) {
            float p = sr[k];
            float4 vv = *(const float4*)(vp + k*DK_);
            a.x += p*vv.x; a.y += p*vv.y; a.z += p*vv.z; a.w += p*vv.w;
        }
        *(float4*)(ctx + base + qi*DD + dg) = a;
    }
}

// ---------------- host launcher ----------------
extern "C" void kernel_launch(void* const* d_in, const int* in_sizes, int n_in,
                              void* d_out, int out_size)
{
    (void)in_sizes; (void)n_in; (void)out_size;
    const int*   x         = (const int*)  d_in[0];
    const float* times     = (const float*)d_in[1];
    const float* token_emb = (const float*)d_in[2];
    const float* pos_emb   = (const float*)d_in[3];
    const float* sel_w     = (const float*)d_in[4];
    const float* sel_b     = (const float*)d_in[5];
    const float* time_w    = (const float*)d_in[6];
    const float* time_b    = (const float*)d_in[7];
    const float* per_w     = (const float*)d_in[8];
    const float* per_b     = (const float*)d_in[9];
    const float* Wq        = (const float*)d_in[10];
    const float* Wk        = (const float*)d_in[11];
    const float* Wt        = (const float*)d_in[12];
    const float* Wv        = (const float*)d_in[13];
    const float* Wo        = (const float*)d_in[14];
    const float* bq        = (const float*)d_in[15];
    const float* bk        = (const float*)d_in[16];
    const float* bt        = (const float*)d_in[17];
    const float* bv        = (const float*)d_in[18];
    const float* bo        = (const float*)d_in[19];
    const float* mask_log  = (const float*)d_in[20];
    const float* ln1_a     = (const float*)d_in[21];
    const float* ln1_b     = (const float*)d_in[22];
    const float* ln2_a     = (const float*)d_in[23];
    const float* ln2_b     = (const float*)d_in[24];
    const float* ffn_w1    = (const float*)d_in[25];
    const float* ffn_b1    = (const float*)d_in[26];
    const float* ffn_w2    = (const float*)d_in[27];
    const float* ffn_b2    = (const float*)d_in[28];
    const float* out_w     = (const float*)d_in[29];
    const float* out_b     = (const float*)d_in[30];
    float* out = (float*)d_out;

    float *ph,*ptemb,*phn,*pq,*pk1,*pk2,*pv,*pctx,*pffn;
    cudaGetSymbolAddress((void**)&ph,    g_h);
    cudaGetSymbolAddress((void**)&ptemb, g_temb);
    cudaGetSymbolAddress((void**)&phn,   g_hn);
    cudaGetSymbolAddress((void**)&pq,    g_q);
    cudaGetSymbolAddress((void**)&pk1,   g_k1);
    cudaGetSymbolAddress((void**)&pk2,   g_k2);
    cudaGetSymbolAddress((void**)&pv,    g_v);
    cudaGetSymbolAddress((void**)&pctx,  g_ctx);
    cudaGetSymbolAddress((void**)&pffn,  g_ffn);

    const int attn_smem = (SS*DK_*2 + DK_*KTP + SS*SS + SS)*(int)sizeof(float); // ~118.6 KB
    cudaFuncSetAttribute(attn_kernel, cudaFuncAttributeMaxDynamicSharedMemorySize, attn_smem);
    const int g2_smem = (2*128*LDS_ + 2*256*LDS_ + 8*256)*(int)sizeof(float);    // 69,632 B
    cudaFuncSetAttribute(gemm2_tf32, cudaFuncAttributeMaxDynamicSharedMemorySize, g2_smem);

    embed_kernel<<<MM, 256>>>(x, times, token_emb, pos_emb, sel_w, sel_b,
                              time_w, time_b, per_w, per_b);

    dim3 gD(2, 25);            // 128x128 tiles, N=256
    dim3 gQKTV(2, 25, 4);      // 4 fused projections
    for (int l = 0; l < LL; l++) {
        ln_kernel<<<MM, 256>>>(ph, ln1_a + l*DD, ln1_b + l*DD, phn);
        qktv_gemm<<<gQKTV, 256>>>(phn, ptemb,
                                  Wq + (size_t)l*DD*DD, Wk + (size_t)l*DD*DD,
                                  Wt + (size_t)l*DD*DD, Wv + (size_t)l*DD*DD,
                                  bq + l*DD, bk + l*DD, bt + l*DD, bv + l*DD,
                                  pq, pk1, pk2, pv);
        attn_kernel<<<dim3(HH, BB), 512, attn_smem>>>(pq, pk1, pk2, pv, x,
                                                      mask_log + l*SS*SS, pctx);
        gemm_tf32<<<gD, 256>>>(pctx, Wo + (size_t)l*DD*DD, bo + l*DD, ph, ph, DD, DD, 2);
        ln_kernel<<<MM, 256>>>(ph, ln2_a + l*DD, ln2_b + l*DD, phn);
        gemm2_tf32<<<dim3(4, 25), 256, g2_smem>>>(phn, ffn_w1 + (size_t)l*DFF_*DD,
                                                  ffn_b1 + l*DFF_, pffn, DFF_, DD, 1);
        gemm_tf32<<<gD, 256>>>(pffn, ffn_w2 + (size_t)l*DD*DFF_, ffn_b2 + l*DD, ph, ph, DD, DFF_, 2);
    }
    gemm2_tf32<<<dim3(196, 25), 256, g2_smem>>>(ph, out_w, out_b, out, NOUT, DD, 0);
}

// round 6
// speedup vs baseline: 1.1305x; 1.1305x over previous
#include <cuda_runtime.h>
#include <mma.h>
#include <math.h>
#include <stdint.h>
using namespace nvcuda;

// Problem constants
#define BB   32
#define SS   100
#define DD   256
#define HH   4
#define DK_  64
#define LL   3
#define MM   (BB*SS)      // 3200
#define DFF_ 1024
#define NOUT 50001

// ---------------- scratch (no allocation allowed -> device globals) ----------------
__device__ float g_h[MM*DD];
__device__ float g_temb[MM*DD];
__device__ float g_hn[MM*DD];
__device__ float g_q[MM*DD];
__device__ float g_k1[MM*DD];
__device__ float g_k2[MM*DD];
__device__ float g_v[MM*DD];
__device__ float g_ctx[MM*DD];
__device__ float g_ffn[MM*DFF_];

// ---------------- embedding + time embedding ----------------
__global__ void embed_kernel(const int* __restrict__ x, const float* __restrict__ times,
                             const float* __restrict__ token_emb, const float* __restrict__ pos_emb,
                             const float* __restrict__ sel_w, const float* __restrict__ sel_b,
                             const float* __restrict__ time_w, const float* __restrict__ time_b,
                             const float* __restrict__ per_w, const float* __restrict__ per_b)
{
    int bs = blockIdx.x;
    int s  = bs % SS;
    int d  = threadIdx.x;
    __shared__ float g[64];
    float tval = times[bs];
    if (d < 64) {
        float t = tval * (1.0f/180.0f) * sel_w[d] + sel_b[d];
        g[d] = 1.0f - tanhf(t*t);
    }
    __syncthreads();
    float ang = 2.0f * 3.14159265358979323846f * tval / 24.0f;
    float sa = sinf(ang), ca = cosf(ang);
    float feat = time_b[d];
    const float* tw = time_w + d*64;
    #pragma unroll 16
    for (int j = 0; j < 64; j++) feat += g[j] * tw[j];
    float per = sa*per_w[d*2+0] + ca*per_w[d*2+1] + per_b[d];
    g_temb[bs*DD + d] = feat + per;
    int tok = x[bs];
    g_h[bs*DD + d] = token_emb[(size_t)tok*DD + d] + pos_emb[s*DD + d];
}

// ---------------- LayerNorm (torch variant: unbiased std, eps added to std) ----------------
__global__ void ln_kernel(const float* __restrict__ x, const float* __restrict__ a,
                          const float* __restrict__ b, float* __restrict__ y)
{
    int row = blockIdx.x;
    int d = threadIdx.x;
    int lane = d & 31, warp = d >> 5;
    __shared__ float ws1[8], ws2[8];
    float v = x[row*DD + d];
    float s = v;
    #pragma unroll
    for (int o = 16; o > 0; o >>= 1) s += __shfl_xor_sync(0xffffffff, s, o);
    if (lane == 0) ws1[warp] = s;
    __syncthreads();
    float tot = 0.f;
    #pragma unroll
    for (int i = 0; i < 8; i++) tot += ws1[i];
    float mean = tot * (1.0f/DD);
    float diff = v - mean;
    float s2 = diff*diff;
    #pragma unroll
    for (int o = 16; o > 0; o >>= 1) s2 += __shfl_xor_sync(0xffffffff, s2, o);
    if (lane == 0) ws2[warp] = s2;
    __syncthreads();
    float tot2 = 0.f;
    #pragma unroll
    for (int i = 0; i < 8; i++) tot2 += ws2[i];
    float stdv = sqrtf(tot2 * (1.0f/(DD-1)));
    y[row*DD + d] = a[d]*diff/(stdv + 1e-6f) + b[d];
}

// ---------------- GELU ----------------
__device__ __forceinline__ float gelu_f(float x) {
    const float c = 0.7978845608028654f;   // sqrt(2/pi)
    float x3 = x*x*x;
    return 0.5f*x*(1.0f + tanhf(c*(x + 0.044715f*x3)));
}

__device__ __forceinline__ float4 tf4(float4 a) {
    return make_float4(wmma::__float_to_tf32(a.x), wmma::__float_to_tf32(a.y),
                       wmma::__float_to_tf32(a.z), wmma::__float_to_tf32(a.w));
}

// ---------------- TF32 WMMA GEMM v1: 128x128 tile, 8 warps, warp 64x32, BK=16, double buffered ----------------
#define BKT  16
#define LDS_ 20

__device__ __forceinline__ void gemm_body(const float* __restrict__ A,
                                          const float* __restrict__ W,
                                          const float* __restrict__ bias,
                                          const float* __restrict__ res,
                                          float* __restrict__ C,
                                          int N, int K, int row0, int col0, int epi)
{
    __shared__ float As[2][128*LDS_];
    __shared__ float Ws[2][128*LDS_];
    __shared__ float stage[8][16*16];

    int tid  = threadIdx.x;
    int warp = tid >> 5;
    int lane = tid & 31;
    int wm = warp & 1;
    int wn = warp >> 1;

    wmma::fragment<wmma::accumulator,16,16,8,float> acc[4][2];
    #pragma unroll
    for (int i = 0; i < 4; i++)
        #pragma unroll
        for (int j = 0; j < 2; j++) wmma::fill_fragment(acc[i][j], 0.0f);

    int lrow = tid >> 1;
    int lcol = (tid & 1) * 8;
    const float* Ag = A + (size_t)(row0 + lrow)*K + lcol;
    int wrow = col0 + lrow;
    const float* Wg = W + (size_t)wrow*K + lcol;
    bool wv = wrow < N;

    float* asp0 = &As[0][lrow*LDS_ + lcol];
    float* wsp0 = &Ws[0][lrow*LDS_ + lcol];
    float* asp1 = &As[1][lrow*LDS_ + lcol];
    float* wsp1 = &Ws[1][lrow*LDS_ + lcol];

    {
        float4 a0 = *(const float4*)(Ag);
        float4 a1 = *(const float4*)(Ag + 4);
        float4 w0 = wv ? *(const float4*)(Wg)     : make_float4(0.f,0.f,0.f,0.f);
        float4 w1 = wv ? *(const float4*)(Wg + 4) : make_float4(0.f,0.f,0.f,0.f);
        *(float4*)(asp0)     = tf4(a0); *(float4*)(asp0 + 4) = tf4(a1);
        *(float4*)(wsp0)     = tf4(w0); *(float4*)(wsp0 + 4) = tf4(w1);
    }
    __syncthreads();

    int buf = 0;
    for (int kk = BKT; kk <= K; kk += BKT) {
        float4 na0, na1, nw0, nw1;
        bool more = (kk < K);
        if (more) {
            na0 = *(const float4*)(Ag + kk);
            na1 = *(const float4*)(Ag + kk + 4);
            nw0 = wv ? *(const float4*)(Wg + kk)     : make_float4(0.f,0.f,0.f,0.f);
            nw1 = wv ? *(const float4*)(Wg + kk + 4) : make_float4(0.f,0.f,0.f,0.f);
        }
        const float* Ab = &As[buf][0];
        const float* Wb = &Ws[buf][0];
        #pragma unroll
        for (int ks = 0; ks < BKT; ks += 8) {
            wmma::fragment<wmma::matrix_a,16,16,8,wmma::precision::tf32,wmma::row_major> af[4];
            wmma::fragment<wmma::matrix_b,16,16,8,wmma::precision::tf32,wmma::col_major> bf[2];
            #pragma unroll
            for (int i = 0; i < 4; i++)
                wmma::load_matrix_sync(af[i], Ab + (wm*64 + i*16)*LDS_ + ks, LDS_);
            #pragma unroll
            for (int j = 0; j < 2; j++)
                wmma::load_matrix_sync(bf[j], Wb + (wn*32 + j*16)*LDS_ + ks, LDS_);
            #pragma unroll
            for (int i = 0; i < 4; i++)
                #pragma unroll
                for (int j = 0; j < 2; j++)
                    wmma::mma_sync(acc[i][j], af[i], bf[j], acc[i][j]);
        }
        if (more) {
            float* ad = buf ? asp0 : asp1;
            float* wd = buf ? wsp0 : wsp1;
            *(float4*)(ad)     = tf4(na0); *(float4*)(ad + 4) = tf4(na1);
            *(float4*)(wd)     = tf4(nw0); *(float4*)(wd + 4) = tf4(nw1);
            __syncthreads();
            buf ^= 1;
        }
    }

    float* st = stage[warp];
    int r  = lane >> 1;
    int c0 = (lane & 1) * 8;
    #pragma unroll
    for (int i = 0; i < 4; i++) {
        #pragma unroll
        for (int j = 0; j < 2; j++) {
            wmma::store_matrix_sync(st, acc[i][j], 16, wmma::mem_row_major);
            __syncwarp();
            int grow  = row0 + wm*64 + i*16 + r;
            int gcolb = col0 + wn*32 + j*16 + c0;
            #pragma unroll
            for (int c = 0; c < 8; c++) {
                int gc = gcolb + c;
                if (gc < N) {
                    float v = st[r*16 + c0 + c] + bias[gc];
                    if (epi == 1) v = gelu_f(v);
                    else if (epi == 2) v += res[(size_t)grow*N + gc];
                    C[(size_t)grow*N + gc] = v;
                }
            }
            __syncwarp();
        }
    }
}

__global__ void __launch_bounds__(256) gemm_tf32(const float* __restrict__ A,
                                                 const float* __restrict__ W,
                                                 const float* __restrict__ bias,
                                                 const float* __restrict__ res,
                                                 float* __restrict__ C, int N, int K, int epi)
{
    gemm_body(A, W, bias, res, C, N, K, blockIdx.y*128, blockIdx.x*128, epi);
}

__global__ void __launch_bounds__(256) qktv_gemm(const float* __restrict__ hn,
                                                 const float* __restrict__ temb,
                                                 const float* __restrict__ Wq, const float* __restrict__ Wk,
                                                 const float* __restrict__ Wt, const float* __restrict__ Wv,
                                                 const float* __restrict__ bq, const float* __restrict__ bk,
                                                 const float* __restrict__ bt, const float* __restrict__ bv,
                                                 float* __restrict__ q, float* __restrict__ k1,
                                                 float* __restrict__ k2, float* __restrict__ v)
{
    int z = blockIdx.z;
    const float* A = (z == 2) ? temb : hn;
    const float* W = (z == 0) ? Wq : (z == 1) ? Wk : (z == 2) ? Wt : Wv;
    const float* b = (z == 0) ? bq : (z == 1) ? bk : (z == 2) ? bt : bv;
    float*       C = (z == 0) ? q  : (z == 1) ? k1 : (z == 2) ? k2 : v;
    gemm_body(A, W, b, nullptr, C, DD, DD, blockIdx.y*128, blockIdx.x*128, 0);
}

// ---------------- TF32 WMMA GEMM v2: 128x128 tile, 4 warps, warp 64x64, BK=16, double buffered ----
// Higher MMA:LDS ratio (16 MMAs per 8 frag loads per ks-step) for the big-N GEMMs.
__global__ void __launch_bounds__(128) gemm_w64(const float* __restrict__ A,
                                                const float* __restrict__ W,
                                                const float* __restrict__ bias,
                                                float* __restrict__ C,
                                                int N, int K, int epi)
{
    __shared__ float As[2][128*LDS_];
    __shared__ float Ws[2][128*LDS_];
    __shared__ float stage[4][16*16];

    int row0 = blockIdx.y * 128, col0 = blockIdx.x * 128;
    int tid  = threadIdx.x;           // 128 threads, 4 warps
    int warp = tid >> 5;
    int lane = tid & 31;
    int wm = warp & 1;                // 64-row half
    int wn = warp >> 1;               // 64-col half

    wmma::fragment<wmma::accumulator,16,16,8,float> acc[4][4];
    #pragma unroll
    for (int i = 0; i < 4; i++)
        #pragma unroll
        for (int j = 0; j < 4; j++) wmma::fill_fragment(acc[i][j], 0.0f);

    // loads: thread -> one row of A tile and one row of W tile, 16 floats each
    const float* Ag = A + (size_t)(row0 + tid)*K;
    int wrow = col0 + tid;
    const float* Wg = W + (size_t)wrow*K;
    bool wv = wrow < N;
    const float4 z4 = make_float4(0.f,0.f,0.f,0.f);

    float* asp0 = &As[0][tid*LDS_];
    float* wsp0 = &Ws[0][tid*LDS_];
    float* asp1 = &As[1][tid*LDS_];
    float* wsp1 = &Ws[1][tid*LDS_];

    {
        float4 a0 = *(const float4*)(Ag);
        float4 a1 = *(const float4*)(Ag + 4);
        float4 a2 = *(const float4*)(Ag + 8);
        float4 a3 = *(const float4*)(Ag + 12);
        float4 w0 = wv ? *(const float4*)(Wg)      : z4;
        float4 w1 = wv ? *(const float4*)(Wg + 4)  : z4;
        float4 w2 = wv ? *(const float4*)(Wg + 8)  : z4;
        float4 w3 = wv ? *(const float4*)(Wg + 12) : z4;
        *(float4*)(asp0)      = tf4(a0); *(float4*)(asp0 + 4)  = tf4(a1);
        *(float4*)(asp0 + 8)  = tf4(a2); *(float4*)(asp0 + 12) = tf4(a3);
        *(float4*)(wsp0)      = tf4(w0); *(float4*)(wsp0 + 4)  = tf4(w1);
        *(float4*)(wsp0 + 8)  = tf4(w2); *(float4*)(wsp0 + 12) = tf4(w3);
    }
    __syncthreads();

    int buf = 0;
    for (int kk = BKT; kk <= K; kk += BKT) {
        float4 na0, na1, na2, na3, nw0, nw1, nw2, nw3;
        bool more = (kk < K);
        if (more) {
            na0 = *(const float4*)(Ag + kk);
            na1 = *(const float4*)(Ag + kk + 4);
            na2 = *(const float4*)(Ag + kk + 8);
            na3 = *(const float4*)(Ag + kk + 12);
            nw0 = wv ? *(const float4*)(Wg + kk)      : z4;
            nw1 = wv ? *(const float4*)(Wg + kk + 4)  : z4;
            nw2 = wv ? *(const float4*)(Wg + kk + 8)  : z4;
            nw3 = wv ? *(const float4*)(Wg + kk + 12) : z4;
        }
        const float* Ab = &As[buf][0];
        const float* Wb = &Ws[buf][0];
        #pragma unroll
        for (int ks = 0; ks < BKT; ks += 8) {
            wmma::fragment<wmma::matrix_a,16,16,8,wmma::precision::tf32,wmma::row_major> af[4];
            wmma::fragment<wmma::matrix_b,16,16,8,wmma::precision::tf32,wmma::col_major> bf[4];
            #pragma unroll
            for (int i = 0; i < 4; i++)
                wmma::load_matrix_sync(af[i], Ab + (wm*64 + i*16)*LDS_ + ks, LDS_);
            #pragma unroll
            for (int j = 0; j < 4; j++)
                wmma::load_matrix_sync(bf[j], Wb + (wn*64 + j*16)*LDS_ + ks, LDS_);
            #pragma unroll
            for (int i = 0; i < 4; i++)
                #pragma unroll
                for (int j = 0; j < 4; j++)
                    wmma::mma_sync(acc[i][j], af[i], bf[j], acc[i][j]);
        }
        if (more) {
            float* ad = buf ? asp0 : asp1;
            float* wd = buf ? wsp0 : wsp1;
            *(float4*)(ad)      = tf4(na0); *(float4*)(ad + 4)  = tf4(na1);
            *(float4*)(ad + 8)  = tf4(na2); *(float4*)(ad + 12) = tf4(na3);
            *(float4*)(wd)      = tf4(nw0); *(float4*)(wd + 4)  = tf4(nw1);
            *(float4*)(wd + 8)  = tf4(nw2); *(float4*)(wd + 12) = tf4(nw3);
            __syncthreads();
            buf ^= 1;
        }
    }

    float* st = stage[warp];
    int r  = lane >> 1;
    int c0 = (lane & 1) * 8;
    #pragma unroll
    for (int i = 0; i < 4; i++) {
        #pragma unroll
        for (int j = 0; j < 4; j++) {
            wmma::store_matrix_sync(st, acc[i][j], 16, wmma::mem_row_major);
            __syncwarp();
            int grow  = row0 + wm*64 + i*16 + r;
            int gcolb = col0 + wn*64 + j*16 + c0;
            #pragma unroll
            for (int c = 0; c < 8; c++) {
                int gc = gcolb + c;
                if (gc < N) {
                    float v = st[r*16 + c0 + c] + bias[gc];
                    if (epi == 1) v = gelu_f(v);
                    C[(size_t)grow*N + gc] = v;
                }
            }
            __syncwarp();
        }
    }
}

// ---------------- attention: one block per (b,h), 512 threads, combined-K ----------------
#define KTP 104

__global__ void __launch_bounds__(512) attn_kernel(
        const float* __restrict__ q, const float* __restrict__ k1,
        const float* __restrict__ k2, const float* __restrict__ v,
        const int* __restrict__ x, const float* __restrict__ ml,
        float* __restrict__ ctx)
{
    extern __shared__ float sm[];
    float* qs  = sm;
    float* vs  = qs  + SS*DK_;
    float* kct = vs  + SS*DK_;
    float* sc  = kct + DK_*KTP;
    float* offs= sc + SS*SS;
    int h = blockIdx.x, b = blockIdx.y;
    int tid = threadIdx.x;
    int lane = tid & 31, warp = tid >> 5;
    int base = b*SS*DD + h*DK_;

    for (int idx = tid; idx < SS*DK_; idx += 512) {
        int s = idx >> 6, d = idx & 63;
        int gi = base + s*DD + d;
        qs[idx] = q[gi];
        vs[idx] = v[gi];
        bool kp = x[b*SS + s] > 0;
        float k2v = k2[gi];
        kct[d*KTP + s] = kp ? (k1[gi] + k2v) : k2v;
    }
    if (tid < SS) offs[tid] = (x[b*SS + tid] > 0) ? 0.0f : -1e9f;
    __syncthreads();

    const float scale = 0.125f;
    for (int g = tid; g < SS*25; g += 512) {
        int qi = g / 25;
        int kg = (g - qi*25) * 4;
        const float* qp = qs + qi*DK_;
        float4 s1 = make_float4(0.f,0.f,0.f,0.f);
        #pragma unroll 8
        for (int d = 0; d < DK_; d++) {
            float qv = qp[d];
            float4 b1 = *(const float4*)(kct + d*KTP + kg);
            s1.x += qv*b1.x; s1.y += qv*b1.y; s1.z += qv*b1.z; s1.w += qv*b1.w;
        }
        float* sr = sc + qi*SS + kg;
        const float* op = offs + kg;
        sr[0] = s1.x*scale + op[0];
        sr[1] = s1.y*scale + op[1];
        sr[2] = s1.z*scale + op[2];
        sr[3] = s1.w*scale + op[3];
    }
    __syncthreads();

    for (int r = warp; r < SS; r += 16) {
        float* row = sc + r*SS;
        float mx = -1e30f;
        for (int c = lane; c < SS; c += 32) mx = fmaxf(mx, row[c]);
        #pragma unroll
        for (int o = 16; o > 0; o >>= 1) mx = fmaxf(mx, __shfl_xor_sync(0xffffffff, mx, o));
        float sum = 0.f;
        for (int c = lane; c < SS; c += 32) {
            float e = __expf(row[c] - mx);
            row[c] = e; sum += e;
        }
        #pragma unroll
        for (int o = 16; o > 0; o >>= 1) sum += __shfl_xor_sync(0xffffffff, sum, o);
        float inv = 1.0f / sum;
        const float* mlr = ml + r*SS;
        for (int c = lane; c < SS; c += 32) {
            float z = mlr[c];
            float sg = 1.0f / (1.0f + __expf(-z));
            row[c] *= inv * sg;
        }
    }
    __syncthreads();

    for (int o = tid; o < SS*16; o += 512) {
        int qi = o >> 4;
        int dg = (o & 15) * 4;
        const float* sr = sc + qi*SS;
        const float* vp = vs + dg;
        float4 a = make_float4(0.f,0.f,0.f,0.f);
        #pragma unroll 4
        for (int k = 0; k < SS; k++) {
            float p = sr[k];
            float4 vv = *(const float4*)(vp + k*DK_);
            a.x += p*vv.x; a.y += p*vv.y; a.z += p*vv.z; a.w += p*vv.w;
        }
        *(float4*)(ctx + base + qi*DD + dg) = a;
    }
}

// ---------------- host launcher ----------------
extern "C" void kernel_launch(void* const* d_in, const int* in_sizes, int n_in,
                              void* d_out, int out_size)
{
    (void)in_sizes; (void)n_in; (void)out_size;
    const int*   x         = (const int*)  d_in[0];
    const float* times     = (const float*)d_in[1];
    const float* token_emb = (const float*)d_in[2];
    const float* pos_emb   = (const float*)d_in[3];
    const float* sel_w     = (const float*)d_in[4];
    const float* sel_b     = (const float*)d_in[5];
    const float* time_w    = (const float*)d_in[6];
    const float* time_b    = (const float*)d_in[7];
    const float* per_w     = (const float*)d_in[8];
    const float* per_b     = (const float*)d_in[9];
    const float* Wq        = (const float*)d_in[10];
    const float* Wk        = (const float*)d_in[11];
    const float* Wt        = (const float*)d_in[12];
    const float* Wv        = (const float*)d_in[13];
    const float* Wo        = (const float*)d_in[14];
    const float* bq        = (const float*)d_in[15];
    const float* bk        = (const float*)d_in[16];
    const float* bt        = (const float*)d_in[17];
    const float* bv        = (const float*)d_in[18];
    const float* bo        = (const float*)d_in[19];
    const float* mask_log  = (const float*)d_in[20];
    const float* ln1_a     = (const float*)d_in[21];
    const float* ln1_b     = (const float*)d_in[22];
    const float* ln2_a     = (const float*)d_in[23];
    const float* ln2_b     = (const float*)d_in[24];
    const float* ffn_w1    = (const float*)d_in[25];
    const float* ffn_b1    = (const float*)d_in[26];
    const float* ffn_w2    = (const float*)d_in[27];
    const float* ffn_b2    = (const float*)d_in[28];
    const float* out_w     = (const float*)d_in[29];
    const float* out_b     = (const float*)d_in[30];
    float* out = (float*)d_out;

    float *ph,*ptemb,*phn,*pq,*pk1,*pk2,*pv,*pctx,*pffn;
    cudaGetSymbolAddress((void**)&ph,    g_h);
    cudaGetSymbolAddress((void**)&ptemb, g_temb);
    cudaGetSymbolAddress((void**)&phn,   g_hn);
    cudaGetSymbolAddress((void**)&pq,    g_q);
    cudaGetSymbolAddress((void**)&pk1,   g_k1);
    cudaGetSymbolAddress((void**)&pk2,   g_k2);
    cudaGetSymbolAddress((void**)&pv,    g_v);
    cudaGetSymbolAddress((void**)&pctx,  g_ctx);
    cudaGetSymbolAddress((void**)&pffn,  g_ffn);

    const int attn_smem = (SS*DK_*2 + DK_*KTP + SS*SS + SS)*(int)sizeof(float);
    cudaFuncSetAttribute(attn_kernel, cudaFuncAttributeMaxDynamicSharedMemorySize, attn_smem);

    embed_kernel<<<MM, 256>>>(x, times, token_emb, pos_emb, sel_w, sel_b,
                              time_w, time_b, per_w, per_b);

    dim3 gD(2, 25);            // 128x128 tiles, N=256
    dim3 gQKTV(2, 25, 4);
    for (int l = 0; l < LL; l++) {
        ln_kernel<<<MM, 256>>>(ph, ln1_a + l*DD, ln1_b + l*DD, phn);
        qktv_gemm<<<gQKTV, 256>>>(phn, ptemb,
                                  Wq + (size_t)l*DD*DD, Wk + (size_t)l*DD*DD,
                                  Wt + (size_t)l*DD*DD, Wv + (size_t)l*DD*DD,
                                  bq + l*DD, bk + l*DD, bt + l*DD, bv + l*DD,
                                  pq, pk1, pk2, pv);
        attn_kernel<<<dim3(HH, BB), 512, attn_smem>>>(pq, pk1, pk2, pv, x,
                                                      mask_log + l*SS*SS, pctx);
        gemm_tf32<<<gD, 256>>>(pctx, Wo + (size_t)l*DD*DD, bo + l*DD, ph, ph, DD, DD, 2);
        ln_kernel<<<MM, 256>>>(ph, ln2_a + l*DD, ln2_b + l*DD, phn);
        gemm_w64<<<dim3(8, 25), 128>>>(phn, ffn_w1 + (size_t)l*DFF_*DD,
                                       ffn_b1 + l*DFF_, pffn, DFF_, DD, 1);
        gemm_tf32<<<gD, 256>>>(pffn, ffn_w2 + (size_t)l*DD*DFF_, ffn_b2 + l*DD, ph, ph, DD, DFF_, 2);
    }
    gemm_w64<<<dim3(391, 25), 128>>>(ph, out_w, out_b, out, NOUT, DD, 0);
}

// round 7
// speedup vs baseline: 1.4037x; 1.2417x over previous
#include <cuda_runtime.h>
#include <mma.h>
#include <math.h>
#include <stdint.h>
using namespace nvcuda;

// Problem constants
#define BB   32
#define SS   100
#define DD   256
#define HH   4
#define DK_  64
#define LL   3
#define MM   (BB*SS)      // 3200
#define DFF_ 1024
#define NOUT 50001

// ---------------- scratch (no allocation allowed -> device globals) ----------------
__device__ float g_h[MM*DD];
__device__ float g_temb[MM*DD];
__device__ float g_hn[MM*DD];
__device__ float g_q[MM*DD];
__device__ float g_k1[MM*DD];
__device__ float g_k2[MM*DD];
__device__ float g_v[MM*DD];
__device__ float g_ctx[MM*DD];
__device__ float g_ffn[MM*DFF_];

// ---------------- embedding + time embedding ----------------
__global__ void embed_kernel(const int* __restrict__ x, const float* __restrict__ times,
                             const float* __restrict__ token_emb, const float* __restrict__ pos_emb,
                             const float* __restrict__ sel_w, const float* __restrict__ sel_b,
                             const float* __restrict__ time_w, const float* __restrict__ time_b,
                             const float* __restrict__ per_w, const float* __restrict__ per_b)
{
    int bs = blockIdx.x;
    int s  = bs % SS;
    int d  = threadIdx.x;
    __shared__ float g[64];
    float tval = times[bs];
    if (d < 64) {
        float t = tval * (1.0f/180.0f) * sel_w[d] + sel_b[d];
        g[d] = 1.0f - tanhf(t*t);
    }
    __syncthreads();
    float ang = 2.0f * 3.14159265358979323846f * tval / 24.0f;
    float sa = sinf(ang), ca = cosf(ang);
    float feat = time_b[d];
    const float* tw = time_w + d*64;
    #pragma unroll 16
    for (int j = 0; j < 64; j++) feat += g[j] * tw[j];
    float per = sa*per_w[d*2+0] + ca*per_w[d*2+1] + per_b[d];
    g_temb[bs*DD + d] = feat + per;
    int tok = x[bs];
    g_h[bs*DD + d] = token_emb[(size_t)tok*DD + d] + pos_emb[s*DD + d];
}

// ---------------- LayerNorm (torch variant: unbiased std, eps added to std) ----------------
__global__ void ln_kernel(const float* __restrict__ x, const float* __restrict__ a,
                          const float* __restrict__ b, float* __restrict__ y)
{
    int row = blockIdx.x;
    int d = threadIdx.x;
    int lane = d & 31, warp = d >> 5;
    __shared__ float ws1[8], ws2[8];
    float v = x[row*DD + d];
    float s = v;
    #pragma unroll
    for (int o = 16; o > 0; o >>= 1) s += __shfl_xor_sync(0xffffffff, s, o);
    if (lane == 0) ws1[warp] = s;
    __syncthreads();
    float tot = 0.f;
    #pragma unroll
    for (int i = 0; i < 8; i++) tot += ws1[i];
    float mean = tot * (1.0f/DD);
    float diff = v - mean;
    float s2 = diff*diff;
    #pragma unroll
    for (int o = 16; o > 0; o >>= 1) s2 += __shfl_xor_sync(0xffffffff, s2, o);
    if (lane == 0) ws2[warp] = s2;
    __syncthreads();
    float tot2 = 0.f;
    #pragma unroll
    for (int i = 0; i < 8; i++) tot2 += ws2[i];
    float stdv = sqrtf(tot2 * (1.0f/(DD-1)));
    y[row*DD + d] = a[d]*diff/(stdv + 1e-6f) + b[d];
}

// ---------------- GELU ----------------
__device__ __forceinline__ float gelu_f(float x) {
    const float c = 0.7978845608028654f;   // sqrt(2/pi)
    float x3 = x*x*x;
    return 0.5f*x*(1.0f + tanhf(c*(x + 0.044715f*x3)));
}

__device__ __forceinline__ float4 tf4(float4 a) {
    return make_float4(wmma::__float_to_tf32(a.x), wmma::__float_to_tf32(a.y),
                       wmma::__float_to_tf32(a.z), wmma::__float_to_tf32(a.w));
}

// ---------------- raw mma.m16n8k8 tf32 GEMM ----------------
// Block tile 128x128, 8 warps as 2(M)x4(N), warp tile 64x32, BK=16, double buffered.
// Permuted smem layouts so each lane's fragment is one vector load:
//   A: [s(k8)][t(m16)][lane][4]  -> frag = LDS.128
//   B: [s(k8)][u(n8)][lane][2]   -> frag = LDS.64
// Fragment maps (PTX m16n8k8): A lane holds (r,c),(r+8,c),(r,c+4),(r+8,c+4), r=lane>>2,c=lane&3
//                              B lane holds (k,n)=(lane&3, lane>>2) and k+4
//                              C lane holds (r,2c),(r,2c+1),(r+8,2c),(r+8,2c+1)
__device__ __forceinline__ void mma_step(float* c, const uint32_t* a, const uint32_t* b) {
    asm volatile("mma.sync.aligned.m16n8k8.row.col.f32.tf32.tf32.f32 "
        "{%0,%1,%2,%3}, {%4,%5,%6,%7}, {%8,%9}, {%0,%1,%2,%3};"
        : "+f"(c[0]), "+f"(c[1]), "+f"(c[2]), "+f"(c[3])
        : "r"(a[0]), "r"(a[1]), "r"(a[2]), "r"(a[3]), "r"(b[0]), "r"(b[1]));
}

__device__ __forceinline__ void gemm_mma_body(const float* __restrict__ A,
                                              const float* __restrict__ W,
                                              const float* __restrict__ bias,
                                              const float* __restrict__ res,
                                              float* __restrict__ C,
                                              int N, int K, int row0, int col0, int epi)
{
    __shared__ float As[2][2048];
    __shared__ float Bs[2][2048];
    int tid = threadIdx.x;
    int warp = tid >> 5, lane = tid & 31;
    int wm = warp & 1, wn = warp >> 1;

    float acc[4][4][4];
    #pragma unroll
    for (int i = 0; i < 4; i++)
        #pragma unroll
        for (int j = 0; j < 4; j++)
            #pragma unroll
            for (int q = 0; q < 4; q++) acc[i][j][q] = 0.f;

    // loaders: thread -> A row lrow, k-half sK (8 floats); same for W
    int lrow = tid >> 1;
    int sK   = tid & 1;
    const float* Ag = A + (size_t)(row0 + lrow)*K + sK*8;
    int wrow = col0 + lrow;
    const float* Wg = W + (size_t)wrow*K + sK*8;
    bool wv = wrow < N;

    int t = lrow >> 4, rp = lrow & 15;
    int aoff = ((sK*8 + t)*32 + (rp & 7)*4)*4 + (rp >> 3);
    int u = lrow >> 3, np = lrow & 7;
    int boff = ((sK*16 + u)*32 + np*4)*2;
    const float4 z4 = make_float4(0.f,0.f,0.f,0.f);

    {   // prologue -> buffer 0
        float4 a0 = tf4(*(const float4*)(Ag));
        float4 a1 = tf4(*(const float4*)(Ag + 4));
        float4 w0 = tf4(wv ? *(const float4*)(Wg)     : z4);
        float4 w1 = tf4(wv ? *(const float4*)(Wg + 4) : z4);
        float* ab = &As[0][aoff];
        ab[0]=a0.x; ab[4]=a0.y; ab[8]=a0.z; ab[12]=a0.w;
        ab[2]=a1.x; ab[6]=a1.y; ab[10]=a1.z; ab[14]=a1.w;
        float* bb = &Bs[0][boff];
        bb[0]=w0.x; bb[2]=w0.y; bb[4]=w0.z; bb[6]=w0.w;
        bb[1]=w1.x; bb[3]=w1.y; bb[5]=w1.z; bb[7]=w1.w;
    }
    __syncthreads();

    int buf = 0;
    for (int kk = 16; kk <= K; kk += 16) {
        float4 na0, na1, nw0, nw1;
        bool more = (kk < K);
        if (more) {
            na0 = *(const float4*)(Ag + kk);
            na1 = *(const float4*)(Ag + kk + 4);
            nw0 = wv ? *(const float4*)(Wg + kk)     : z4;
            nw1 = wv ? *(const float4*)(Wg + kk + 4) : z4;
        }
        const float* Ab = As[buf];
        const float* Bb = Bs[buf];
        #pragma unroll
        for (int s = 0; s < 2; s++) {
            uint32_t af[4][4], bf[4][2];
            #pragma unroll
            for (int i = 0; i < 4; i++) {
                float4 v = *(const float4*)(Ab + ((s*8 + wm*4 + i)*32 + lane)*4);
                af[i][0] = __float_as_uint(v.x); af[i][1] = __float_as_uint(v.y);
                af[i][2] = __float_as_uint(v.z); af[i][3] = __float_as_uint(v.w);
            }
            #pragma unroll
            for (int j = 0; j < 4; j++) {
                float2 v = *(const float2*)(Bb + ((s*16 + wn*4 + j)*32 + lane)*2);
                bf[j][0] = __float_as_uint(v.x); bf[j][1] = __float_as_uint(v.y);
            }
            #pragma unroll
            for (int i = 0; i < 4; i++)
                #pragma unroll
                for (int j = 0; j < 4; j++)
                    mma_step(acc[i][j], af[i], bf[j]);
        }
        if (more) {
            float4 ca0 = tf4(na0), ca1 = tf4(na1), cw0 = tf4(nw0), cw1 = tf4(nw1);
            float* ab = &As[buf^1][aoff];
            ab[0]=ca0.x; ab[4]=ca0.y; ab[8]=ca0.z; ab[12]=ca0.w;
            ab[2]=ca1.x; ab[6]=ca1.y; ab[10]=ca1.z; ab[14]=ca1.w;
            float* bb = &Bs[buf^1][boff];
            bb[0]=cw0.x; bb[2]=cw0.y; bb[4]=cw0.z; bb[6]=cw0.w;
            bb[1]=cw1.x; bb[3]=cw1.y; bb[5]=cw1.z; bb[7]=cw1.w;
            __syncthreads();
            buf ^= 1;
        }
    }

    // epilogue: accum regs -> global directly (known lane mapping)
    int r = lane >> 2, c2 = (lane & 3) * 2;
    #pragma unroll
    for (int i = 0; i < 4; i++) {
        int gr = row0 + wm*64 + i*16 + r;
        size_t rb0 = (size_t)gr * N;
        size_t rb1 = (size_t)(gr + 8) * N;
        #pragma unroll
        for (int j = 0; j < 4; j++) {
            int gc = col0 + wn*32 + j*8 + c2;
            const float* cp = acc[i][j];
            if (gc + 1 < N) {
                float b0 = bias[gc], b1 = bias[gc+1];
                float v0 = cp[0] + b0, v1 = cp[1] + b1;
                float v2 = cp[2] + b0, v3 = cp[3] + b1;
                if (epi == 1) { v0 = gelu_f(v0); v1 = gelu_f(v1); v2 = gelu_f(v2); v3 = gelu_f(v3); }
                else if (epi == 2) {
                    v0 += res[rb0 + gc]; v1 += res[rb0 + gc + 1];
                    v2 += res[rb1 + gc]; v3 += res[rb1 + gc + 1];
                }
                C[rb0 + gc] = v0; C[rb0 + gc + 1] = v1;
                C[rb1 + gc] = v2; C[rb1 + gc + 1] = v3;
            } else if (gc < N) {
                float b0 = bias[gc];
                float v0 = cp[0] + b0, v2 = cp[2] + b0;
                if (epi == 1) { v0 = gelu_f(v0); v2 = gelu_f(v2); }
                else if (epi == 2) { v0 += res[rb0 + gc]; v2 += res[rb1 + gc]; }
                C[rb0 + gc] = v0; C[rb1 + gc] = v2;
            }
        }
    }
}

__global__ void __launch_bounds__(256, 2) gemm_mma(const float* __restrict__ A,
                                                   const float* __restrict__ W,
                                                   const float* __restrict__ bias,
                                                   const float* __restrict__ res,
                                                   float* __restrict__ C, int N, int K, int epi)
{
    gemm_mma_body(A, W, bias, res, C, N, K, blockIdx.y*128, blockIdx.x*128, epi);
}

__global__ void __launch_bounds__(256, 2) qktv_gemm(const float* __restrict__ hn,
                                                    const float* __restrict__ temb,
                                                    const float* __restrict__ Wq, const float* __restrict__ Wk,
                                                    const float* __restrict__ Wt, const float* __restrict__ Wv,
                                                    const float* __restrict__ bq, const float* __restrict__ bk,
                                                    const float* __restrict__ bt, const float* __restrict__ bv,
                                                    float* __restrict__ q, float* __restrict__ k1,
                                                    float* __restrict__ k2, float* __restrict__ v)
{
    int z = blockIdx.z;
    const float* A = (z == 2) ? temb : hn;
    const float* W = (z == 0) ? Wq : (z == 1) ? Wk : (z == 2) ? Wt : Wv;
    const float* b = (z == 0) ? bq : (z == 1) ? bk : (z == 2) ? bt : bv;
    float*       C = (z == 0) ? q  : (z == 1) ? k1 : (z == 2) ? k2 : v;
    gemm_mma_body(A, W, b, nullptr, C, DD, DD, blockIdx.y*128, blockIdx.x*128, 0);
}

// ---------------- attention: one block per (b,h), 512 threads, combined-K ----------------
#define KTP 104

__global__ void __launch_bounds__(512) attn_kernel(
        const float* __restrict__ q, const float* __restrict__ k1,
        const float* __restrict__ k2, const float* __restrict__ v,
        const int* __restrict__ x, const float* __restrict__ ml,
        float* __restrict__ ctx)
{
    extern __shared__ float sm[];
    float* qs  = sm;
    float* vs  = qs  + SS*DK_;
    float* kct = vs  + SS*DK_;
    float* sc  = kct + DK_*KTP;
    float* offs= sc + SS*SS;
    int h = blockIdx.x, b = blockIdx.y;
    int tid = threadIdx.x;
    int lane = tid & 31, warp = tid >> 5;
    int base = b*SS*DD + h*DK_;

    for (int idx = tid; idx < SS*DK_; idx += 512) {
        int s = idx >> 6, d = idx & 63;
        int gi = base + s*DD + d;
        qs[idx] = q[gi];
        vs[idx] = v[gi];
        bool kp = x[b*SS + s] > 0;
        float k2v = k2[gi];
        kct[d*KTP + s] = kp ? (k1[gi] + k2v) : k2v;
    }
    if (tid < SS) offs[tid] = (x[b*SS + tid] > 0) ? 0.0f : -1e9f;
    __syncthreads();

    const float scale = 0.125f;
    for (int g = tid; g < SS*25; g += 512) {
        int qi = g / 25;
        int kg = (g - qi*25) * 4;
        const float* qp = qs + qi*DK_;
        float4 s1 = make_float4(0.f,0.f,0.f,0.f);
        #pragma unroll 8
        for (int d = 0; d < DK_; d++) {
            float qv = qp[d];
            float4 b1 = *(const float4*)(kct + d*KTP + kg);
            s1.x += qv*b1.x; s1.y += qv*b1.y; s1.z += qv*b1.z; s1.w += qv*b1.w;
        }
        float* sr = sc + qi*SS + kg;
        const float* op = offs + kg;
        sr[0] = s1.x*scale + op[0];
        sr[1] = s1.y*scale + op[1];
        sr[2] = s1.z*scale + op[2];
        sr[3] = s1.w*scale + op[3];
    }
    __syncthreads();

    for (int r = warp; r < SS; r += 16) {
        float* row = sc + r*SS;
        float mx = -1e30f;
        for (int c = lane; c < SS; c += 32) mx = fmaxf(mx, row[c]);
        #pragma unroll
        for (int o = 16; o > 0; o >>= 1) mx = fmaxf(mx, __shfl_xor_sync(0xffffffff, mx, o));
        float sum = 0.f;
        for (int c = lane; c < SS; c += 32) {
            float e = __expf(row[c] - mx);
            row[c] = e; sum += e;
        }
        #pragma unroll
        for (int o = 16; o > 0; o >>= 1) sum += __shfl_xor_sync(0xffffffff, sum, o);
        float inv = 1.0f / sum;
        const float* mlr = ml + r*SS;
        for (int c = lane; c < SS; c += 32) {
            float z = mlr[c];
            float sg = 1.0f / (1.0f + __expf(-z));
            row[c] *= inv * sg;
        }
    }
    __syncthreads();

    for (int o = tid; o < SS*16; o += 512) {
        int qi = o >> 4;
        int dg = (o & 15) * 4;
        const float* sr = sc + qi*SS;
        const float* vp = vs + dg;
        float4 a = make_float4(0.f,0.f,0.f,0.f);
        #pragma unroll 4
        for (int k = 0; k < SS; k++) {
            float p = sr[k];
            float4 vv = *(const float4*)(vp + k*DK_);
            a.x += p*vv.x; a.y += p*vv.y; a.z += p*vv.z; a.w += p*vv.w;
        }
        *(float4*)(ctx + base + qi*DD + dg) = a;
    }
}

// ---------------- host launcher ----------------
extern "C" void kernel_launch(void* const* d_in, const int* in_sizes, int n_in,
                              void* d_out, int out_size)
{
    (void)in_sizes; (void)n_in; (void)out_size;
    const int*   x         = (const int*)  d_in[0];
    const float* times     = (const float*)d_in[1];
    const float* token_emb = (const float*)d_in[2];
    const float* pos_emb   = (const float*)d_in[3];
    const float* sel_w     = (const float*)d_in[4];
    const float* sel_b     = (const float*)d_in[5];
    const float* time_w    = (const float*)d_in[6];
    const float* time_b    = (const float*)d_in[7];
    const float* per_w     = (const float*)d_in[8];
    const float* per_b     = (const float*)d_in[9];
    const float* Wq        = (const float*)d_in[10];
    const float* Wk        = (const float*)d_in[11];
    const float* Wt        = (const float*)d_in[12];
    const float* Wv        = (const float*)d_in[13];
    const float* Wo        = (const float*)d_in[14];
    const float* bq        = (const float*)d_in[15];
    const float* bk        = (const float*)d_in[16];
    const float* bt        = (const float*)d_in[17];
    const float* bv        = (const float*)d_in[18];
    const float* bo        = (const float*)d_in[19];
    const float* mask_log  = (const float*)d_in[20];
    const float* ln1_a     = (const float*)d_in[21];
    const float* ln1_b     = (const float*)d_in[22];
    const float* ln2_a     = (const float*)d_in[23];
    const float* ln2_b     = (const float*)d_in[24];
    const float* ffn_w1    = (const float*)d_in[25];
    const float* ffn_b1    = (const float*)d_in[26];
    const float* ffn_w2    = (const float*)d_in[27];
    const float* ffn_b2    = (const float*)d_in[28];
    const float* out_w     = (const float*)d_in[29];
    const float* out_b     = (const float*)d_in[30];
    float* out = (float*)d_out;

    float *ph,*ptemb,*phn,*pq,*pk1,*pk2,*pv,*pctx,*pffn;
    cudaGetSymbolAddress((void**)&ph,    g_h);
    cudaGetSymbolAddress((void**)&ptemb, g_temb);
    cudaGetSymbolAddress((void**)&phn,   g_hn);
    cudaGetSymbolAddress((void**)&pq,    g_q);
    cudaGetSymbolAddress((void**)&pk1,   g_k1);
    cudaGetSymbolAddress((void**)&pk2,   g_k2);
    cudaGetSymbolAddress((void**)&pv,    g_v);
    cudaGetSymbolAddress((void**)&pctx,  g_ctx);
    cudaGetSymbolAddress((void**)&pffn,  g_ffn);

    const int attn_smem = (SS*DK_*2 + DK_*KTP + SS*SS + SS)*(int)sizeof(float);
    cudaFuncSetAttribute(attn_kernel, cudaFuncAttributeMaxDynamicSharedMemorySize, attn_smem);

    embed_kernel<<<MM, 256>>>(x, times, token_emb, pos_emb, sel_w, sel_b,
                              time_w, time_b, per_w, per_b);

    dim3 gD(2, 25);            // 128x128 tiles, N=256
    dim3 gF(8, 25);            // N=1024
    dim3 gQKTV(2, 25, 4);
    for (int l = 0; l < LL; l++) {
        ln_kernel<<<MM, 256>>>(ph, ln1_a + l*DD, ln1_b + l*DD, phn);
        qktv_gemm<<<gQKTV, 256>>>(phn, ptemb,
                                  Wq + (size_t)l*DD*DD, Wk + (size_t)l*DD*DD,
                                  Wt + (size_t)l*DD*DD, Wv + (size_t)l*DD*DD,
                                  bq + l*DD, bk + l*DD, bt + l*DD, bv + l*DD,
                                  pq, pk1, pk2, pv);
        attn_kernel<<<dim3(HH, BB), 512, attn_smem>>>(pq, pk1, pk2, pv, x,
                                                      mask_log + l*SS*SS, pctx);
        gemm_mma<<<gD, 256>>>(pctx, Wo + (size_t)l*DD*DD, bo + l*DD, ph, ph, DD, DD, 2);
        ln_kernel<<<MM, 256>>>(ph, ln2_a + l*DD, ln2_b + l*DD, phn);
        gemm_mma<<<gF, 256>>>(phn, ffn_w1 + (size_t)l*DFF_*DD, ffn_b1 + l*DFF_,
                              nullptr, pffn, DFF_, DD, 1);
        gemm_mma<<<gD, 256>>>(pffn, ffn_w2 + (size_t)l*DD*DFF_, ffn_b2 + l*DD, ph, ph, DD, DFF_, 2);
    }
    gemm_mma<<<dim3(391, 25), 256>>>(ph, out_w, out_b, nullptr, out, NOUT, DD, 0);
}

// round 8
// speedup vs baseline: 1.4510x; 1.0337x over previous
#include <cuda_runtime.h>
#include <mma.h>
#include <math.h>
#include <stdint.h>
using namespace nvcuda;

// Problem constants
#define BB   32
#define SS   100
#define SH   50        // q rows per attention block (split 2)
#define DD   256
#define HH   4
#define DK_  64
#define LL   3
#define MM   (BB*SS)      // 3200
#define DFF_ 1024
#define NOUT 50001

// ---------------- scratch (no allocation allowed -> device globals) ----------------
__device__ float g_h[MM*DD];
__device__ float g_temb[MM*DD];
__device__ float g_hn[MM*DD];
__device__ float g_q[MM*DD];
__device__ float g_k1[MM*DD];
__device__ float g_k2[MM*DD];
__device__ float g_v[MM*DD];
__device__ float g_ctx[MM*DD];
__device__ float g_ffn[MM*DFF_];

// ---------------- embedding + time embedding ----------------
__global__ void embed_kernel(const int* __restrict__ x, const float* __restrict__ times,
                             const float* __restrict__ token_emb, const float* __restrict__ pos_emb,
                             const float* __restrict__ sel_w, const float* __restrict__ sel_b,
                             const float* __restrict__ time_w, const float* __restrict__ time_b,
                             const float* __restrict__ per_w, const float* __restrict__ per_b)
{
    int bs = blockIdx.x;
    int s  = bs % SS;
    int d  = threadIdx.x;
    __shared__ float g[64];
    float tval = times[bs];
    if (d < 64) {
        float t = tval * (1.0f/180.0f) * sel_w[d] + sel_b[d];
        g[d] = 1.0f - tanhf(t*t);
    }
    __syncthreads();
    float ang = 2.0f * 3.14159265358979323846f * tval / 24.0f;
    float sa = sinf(ang), ca = cosf(ang);
    float feat = time_b[d];
    const float* tw = time_w + d*64;
    #pragma unroll 16
    for (int j = 0; j < 64; j++) feat += g[j] * tw[j];
    float per = sa*per_w[d*2+0] + ca*per_w[d*2+1] + per_b[d];
    g_temb[bs*DD + d] = feat + per;
    int tok = x[bs];
    g_h[bs*DD + d] = token_emb[(size_t)tok*DD + d] + pos_emb[s*DD + d];
}

// ---------------- LayerNorm (torch variant: unbiased std, eps added to std) ----------------
__global__ void ln_kernel(const float* __restrict__ x, const float* __restrict__ a,
                          const float* __restrict__ b, float* __restrict__ y)
{
    int row = blockIdx.x;
    int d = threadIdx.x;
    int lane = d & 31, warp = d >> 5;
    __shared__ float ws1[8], ws2[8];
    float v = x[row*DD + d];
    float s = v;
    #pragma unroll
    for (int o = 16; o > 0; o >>= 1) s += __shfl_xor_sync(0xffffffff, s, o);
    if (lane == 0) ws1[warp] = s;
    __syncthreads();
    float tot = 0.f;
    #pragma unroll
    for (int i = 0; i < 8; i++) tot += ws1[i];
    float mean = tot * (1.0f/DD);
    float diff = v - mean;
    float s2 = diff*diff;
    #pragma unroll
    for (int o = 16; o > 0; o >>= 1) s2 += __shfl_xor_sync(0xffffffff, s2, o);
    if (lane == 0) ws2[warp] = s2;
    __syncthreads();
    float tot2 = 0.f;
    #pragma unroll
    for (int i = 0; i < 8; i++) tot2 += ws2[i];
    float stdv = sqrtf(tot2 * (1.0f/(DD-1)));
    y[row*DD + d] = a[d]*diff/(stdv + 1e-6f) + b[d];
}

// ---------------- GELU ----------------
__device__ __forceinline__ float gelu_f(float x) {
    const float c = 0.7978845608028654f;   // sqrt(2/pi)
    float x3 = x*x*x;
    return 0.5f*x*(1.0f + tanhf(c*(x + 0.044715f*x3)));
}

__device__ __forceinline__ float4 tf4(float4 a) {
    return make_float4(wmma::__float_to_tf32(a.x), wmma::__float_to_tf32(a.y),
                       wmma::__float_to_tf32(a.z), wmma::__float_to_tf32(a.w));
}

// ---------------- raw mma.m16n8k8 tf32 ----------------
__device__ __forceinline__ void mma_step(float* c, const uint32_t* a, const uint32_t* b) {
    asm volatile("mma.sync.aligned.m16n8k8.row.col.f32.tf32.tf32.f32 "
        "{%0,%1,%2,%3}, {%4,%5,%6,%7}, {%8,%9}, {%0,%1,%2,%3};"
        : "+f"(c[0]), "+f"(c[1]), "+f"(c[2]), "+f"(c[3])
        : "r"(a[0]), "r"(a[1]), "r"(a[2]), "r"(a[3]), "r"(b[0]), "r"(b[1]));
}

// ---------------- GEMM v1: 128x128 tile, 8 warps (2Mx4N), warp 64x32, BK=16, double buffered ----
__device__ __forceinline__ void gemm_mma_body(const float* __restrict__ A,
                                              const float* __restrict__ W,
                                              const float* __restrict__ bias,
                                              const float* __restrict__ res,
                                              float* __restrict__ C,
                                              int N, int K, int row0, int col0, int epi)
{
    __shared__ float As[2][2048];
    __shared__ float Bs[2][2048];
    int tid = threadIdx.x;
    int warp = tid >> 5, lane = tid & 31;
    int wm = warp & 1, wn = warp >> 1;

    float acc[4][4][4];
    #pragma unroll
    for (int i = 0; i < 4; i++)
        #pragma unroll
        for (int j = 0; j < 4; j++)
            #pragma unroll
            for (int q = 0; q < 4; q++) acc[i][j][q] = 0.f;

    int lrow = tid >> 1;
    int sK   = tid & 1;
    const float* Ag = A + (size_t)(row0 + lrow)*K + sK*8;
    int wrow = col0 + lrow;
    const float* Wg = W + (size_t)wrow*K + sK*8;
    bool wv = wrow < N;

    int t = lrow >> 4, rp = lrow & 15;
    int aoff = ((sK*8 + t)*32 + (rp & 7)*4)*4 + (rp >> 3);
    int u = lrow >> 3, np = lrow & 7;
    int boff = ((sK*16 + u)*32 + np*4)*2;
    const float4 z4 = make_float4(0.f,0.f,0.f,0.f);

    {
        float4 a0 = tf4(*(const float4*)(Ag));
        float4 a1 = tf4(*(const float4*)(Ag + 4));
        float4 w0 = tf4(wv ? *(const float4*)(Wg)     : z4);
        float4 w1 = tf4(wv ? *(const float4*)(Wg + 4) : z4);
        float* ab = &As[0][aoff];
        ab[0]=a0.x; ab[4]=a0.y; ab[8]=a0.z; ab[12]=a0.w;
        ab[2]=a1.x; ab[6]=a1.y; ab[10]=a1.z; ab[14]=a1.w;
        float* bb = &Bs[0][boff];
        bb[0]=w0.x; bb[2]=w0.y; bb[4]=w0.z; bb[6]=w0.w;
        bb[1]=w1.x; bb[3]=w1.y; bb[5]=w1.z; bb[7]=w1.w;
    }
    __syncthreads();

    int buf = 0;
    for (int kk = 16; kk <= K; kk += 16) {
        float4 na0, na1, nw0, nw1;
        bool more = (kk < K);
        if (more) {
            na0 = *(const float4*)(Ag + kk);
            na1 = *(const float4*)(Ag + kk + 4);
            nw0 = wv ? *(const float4*)(Wg + kk)     : z4;
            nw1 = wv ? *(const float4*)(Wg + kk + 4) : z4;
        }
        const float* Ab = As[buf];
        const float* Bb = Bs[buf];
        #pragma unroll
        for (int s = 0; s < 2; s++) {
            uint32_t af[4][4], bf[4][2];
            #pragma unroll
            for (int i = 0; i < 4; i++) {
                float4 v = *(const float4*)(Ab + ((s*8 + wm*4 + i)*32 + lane)*4);
                af[i][0] = __float_as_uint(v.x); af[i][1] = __float_as_uint(v.y);
                af[i][2] = __float_as_uint(v.z); af[i][3] = __float_as_uint(v.w);
            }
            #pragma unroll
            for (int j = 0; j < 4; j++) {
                float2 v = *(const float2*)(Bb + ((s*16 + wn*4 + j)*32 + lane)*2);
                bf[j][0] = __float_as_uint(v.x); bf[j][1] = __float_as_uint(v.y);
            }
            #pragma unroll
            for (int i = 0; i < 4; i++)
                #pragma unroll
                for (int j = 0; j < 4; j++)
                    mma_step(acc[i][j], af[i], bf[j]);
        }
        if (more) {
            float4 ca0 = tf4(na0), ca1 = tf4(na1), cw0 = tf4(nw0), cw1 = tf4(nw1);
            float* ab = &As[buf^1][aoff];
            ab[0]=ca0.x; ab[4]=ca0.y; ab[8]=ca0.z; ab[12]=ca0.w;
            ab[2]=ca1.x; ab[6]=ca1.y; ab[10]=ca1.z; ab[14]=ca1.w;
            float* bb = &Bs[buf^1][boff];
            bb[0]=cw0.x; bb[2]=cw0.y; bb[4]=cw0.z; bb[6]=cw0.w;
            bb[1]=cw1.x; bb[3]=cw1.y; bb[5]=cw1.z; bb[7]=cw1.w;
            __syncthreads();
            buf ^= 1;
        }
    }

    int r = lane >> 2, c2 = (lane & 3) * 2;
    #pragma unroll
    for (int i = 0; i < 4; i++) {
        int gr = row0 + wm*64 + i*16 + r;
        size_t rb0 = (size_t)gr * N;
        size_t rb1 = (size_t)(gr + 8) * N;
        #pragma unroll
        for (int j = 0; j < 4; j++) {
            int gc = col0 + wn*32 + j*8 + c2;
            const float* cp = acc[i][j];
            if (gc + 1 < N) {
                float b0 = bias[gc], b1 = bias[gc+1];
                float v0 = cp[0] + b0, v1 = cp[1] + b1;
                float v2 = cp[2] + b0, v3 = cp[3] + b1;
                if (epi == 1) { v0 = gelu_f(v0); v1 = gelu_f(v1); v2 = gelu_f(v2); v3 = gelu_f(v3); }
                else if (epi == 2) {
                    v0 += res[rb0 + gc]; v1 += res[rb0 + gc + 1];
                    v2 += res[rb1 + gc]; v3 += res[rb1 + gc + 1];
                }
                C[rb0 + gc] = v0; C[rb0 + gc + 1] = v1;
                C[rb1 + gc] = v2; C[rb1 + gc + 1] = v3;
            } else if (gc < N) {
                float b0 = bias[gc];
                float v0 = cp[0] + b0, v2 = cp[2] + b0;
                if (epi == 1) { v0 = gelu_f(v0); v2 = gelu_f(v2); }
                else if (epi == 2) { v0 += res[rb0 + gc]; v2 += res[rb1 + gc]; }
                C[rb0 + gc] = v0; C[rb1 + gc] = v2;
            }
        }
    }
}

__global__ void __launch_bounds__(256, 2) gemm_mma(const float* __restrict__ A,
                                                   const float* __restrict__ W,
                                                   const float* __restrict__ bias,
                                                   const float* __restrict__ res,
                                                   float* __restrict__ C, int N, int K, int epi)
{
    gemm_mma_body(A, W, bias, res, C, N, K, blockIdx.y*128, blockIdx.x*128, epi);
}

__global__ void __launch_bounds__(256, 2) qktv_gemm(const float* __restrict__ hn,
                                                    const float* __restrict__ temb,
                                                    const float* __restrict__ Wq, const float* __restrict__ Wk,
                                                    const float* __restrict__ Wt, const float* __restrict__ Wv,
                                                    const float* __restrict__ bq, const float* __restrict__ bk,
                                                    const float* __restrict__ bt, const float* __restrict__ bv,
                                                    float* __restrict__ q, float* __restrict__ k1,
                                                    float* __restrict__ k2, float* __restrict__ v)
{
    int z = blockIdx.z;
    const float* A = (z == 2) ? temb : hn;
    const float* W = (z == 0) ? Wq : (z == 1) ? Wk : (z == 2) ? Wt : Wv;
    const float* b = (z == 0) ? bq : (z == 1) ? bk : (z == 2) ? bt : bv;
    float*       C = (z == 0) ? q  : (z == 1) ? k1 : (z == 2) ? k2 : v;
    gemm_mma_body(A, W, b, nullptr, C, DD, DD, blockIdx.y*128, blockIdx.x*128, 0);
}

// ---------------- GEMM small: 64x64 tile, 4 warps (2Mx2N), warp 32x32, BK=16, double buffered ----
// For N=256 GEMMs (Wo, FFN2): 4x the blocks of the 128x128 kernel -> fills the chip.
__global__ void __launch_bounds__(128) gemm_s(const float* __restrict__ A,
                                              const float* __restrict__ W,
                                              const float* __restrict__ bias,
                                              const float* __restrict__ res,
                                              float* __restrict__ C, int N, int K, int epi)
{
    __shared__ float As[2][1024];
    __shared__ float Bs[2][1024];
    int tid = threadIdx.x;
    int warp = tid >> 5, lane = tid & 31;
    int wm = warp & 1, wn = warp >> 1;
    int row0 = blockIdx.y*64, col0 = blockIdx.x*64;

    float acc[2][4][4];
    #pragma unroll
    for (int i = 0; i < 2; i++)
        #pragma unroll
        for (int j = 0; j < 4; j++)
            #pragma unroll
            for (int q = 0; q < 4; q++) acc[i][j][q] = 0.f;

    int lrow = tid >> 1;          // 0..63
    int sK   = tid & 1;
    const float* Ag = A + (size_t)(row0 + lrow)*K + sK*8;
    int wrow = col0 + lrow;
    const float* Wg = W + (size_t)wrow*K + sK*8;
    bool wv = wrow < N;

    int t = lrow >> 4, rp = lrow & 15;        // t: 0..3
    int aoff = ((sK*4 + t)*32 + (rp & 7)*4)*4 + (rp >> 3);
    int u = lrow >> 3, np = lrow & 7;         // u: 0..7
    int boff = ((sK*8 + u)*32 + np*4)*2;
    const float4 z4 = make_float4(0.f,0.f,0.f,0.f);

    {
        float4 a0 = tf4(*(const float4*)(Ag));
        float4 a1 = tf4(*(const float4*)(Ag + 4));
        float4 w0 = tf4(wv ? *(const float4*)(Wg)     : z4);
        float4 w1 = tf4(wv ? *(const float4*)(Wg + 4) : z4);
        float* ab = &As[0][aoff];
        ab[0]=a0.x; ab[4]=a0.y; ab[8]=a0.z; ab[12]=a0.w;
        ab[2]=a1.x; ab[6]=a1.y; ab[10]=a1.z; ab[14]=a1.w;
        float* bb = &Bs[0][boff];
        bb[0]=w0.x; bb[2]=w0.y; bb[4]=w0.z; bb[6]=w0.w;
        bb[1]=w1.x; bb[3]=w1.y; bb[5]=w1.z; bb[7]=w1.w;
    }
    __syncthreads();

    int buf = 0;
    for (int kk = 16; kk <= K; kk += 16) {
        float4 na0, na1, nw0, nw1;
        bool more = (kk < K);
        if (more) {
            na0 = *(const float4*)(Ag + kk);
            na1 = *(const float4*)(Ag + kk + 4);
            nw0 = wv ? *(const float4*)(Wg + kk)     : z4;
            nw1 = wv ? *(const float4*)(Wg + kk + 4) : z4;
        }
        const float* Ab = As[buf];
        const float* Bb = Bs[buf];
        #pragma unroll
        for (int s = 0; s < 2; s++) {
            uint32_t af[2][4], bf[4][2];
            #pragma unroll
            for (int i = 0; i < 2; i++) {
                float4 v = *(const float4*)(Ab + ((s*4 + wm*2 + i)*32 + lane)*4);
                af[i][0] = __float_as_uint(v.x); af[i][1] = __float_as_uint(v.y);
                af[i][2] = __float_as_uint(v.z); af[i][3] = __float_as_uint(v.w);
            }
            #pragma unroll
            for (int j = 0; j < 4; j++) {
                float2 v = *(const float2*)(Bb + ((s*8 + wn*4 + j)*32 + lane)*2);
                bf[j][0] = __float_as_uint(v.x); bf[j][1] = __float_as_uint(v.y);
            }
            #pragma unroll
            for (int i = 0; i < 2; i++)
                #pragma unroll
                for (int j = 0; j < 4; j++)
                    mma_step(acc[i][j], af[i], bf[j]);
        }
        if (more) {
            float4 ca0 = tf4(na0), ca1 = tf4(na1), cw0 = tf4(nw0), cw1 = tf4(nw1);
            float* ab = &As[buf^1][aoff];
            ab[0]=ca0.x; ab[4]=ca0.y; ab[8]=ca0.z; ab[12]=ca0.w;
            ab[2]=ca1.x; ab[6]=ca1.y; ab[10]=ca1.z; ab[14]=ca1.w;
            float* bb = &Bs[buf^1][boff];
            bb[0]=cw0.x; bb[2]=cw0.y; bb[4]=cw0.z; bb[6]=cw0.w;
            bb[1]=cw1.x; bb[3]=cw1.y; bb[5]=cw1.z; bb[7]=cw1.w;
            __syncthreads();
            buf ^= 1;
        }
    }

    int r = lane >> 2, c2 = (lane & 3) * 2;
    #pragma unroll
    for (int i = 0; i < 2; i++) {
        int gr = row0 + wm*32 + i*16 + r;
        size_t rb0 = (size_t)gr * N;
        size_t rb1 = (size_t)(gr + 8) * N;
        #pragma unroll
        for (int j = 0; j < 4; j++) {
            int gc = col0 + wn*32 + j*8 + c2;
            const float* cp = acc[i][j];
            if (gc + 1 < N) {
                float b0 = bias[gc], b1 = bias[gc+1];
                float v0 = cp[0] + b0, v1 = cp[1] + b1;
                float v2 = cp[2] + b0, v3 = cp[3] + b1;
                if (epi == 1) { v0 = gelu_f(v0); v1 = gelu_f(v1); v2 = gelu_f(v2); v3 = gelu_f(v3); }
                else if (epi == 2) {
                    v0 += res[rb0 + gc]; v1 += res[rb0 + gc + 1];
                    v2 += res[rb1 + gc]; v3 += res[rb1 + gc + 1];
                }
                C[rb0 + gc] = v0; C[rb0 + gc + 1] = v1;
                C[rb1 + gc] = v2; C[rb1 + gc + 1] = v3;
            } else if (gc < N) {
                float b0 = bias[gc];
                float v0 = cp[0] + b0, v2 = cp[2] + b0;
                if (epi == 1) { v0 = gelu_f(v0); v2 = gelu_f(v2); }
                else if (epi == 2) { v0 += res[rb0 + gc]; v2 += res[rb1 + gc]; }
                C[rb0 + gc] = v0; C[rb1 + gc] = v2;
            }
        }
    }
}

// ---------------- attention: grid (H, B, 2) -- each block does 50 query rows ----------------
#define KTP 104

__global__ void __launch_bounds__(512) attn_kernel(
        const float* __restrict__ q, const float* __restrict__ k1,
        const float* __restrict__ k2, const float* __restrict__ v,
        const int* __restrict__ x, const float* __restrict__ ml,
        float* __restrict__ ctx)
{
    extern __shared__ float sm[];
    float* qs  = sm;                    // SH*64
    float* vs  = qs  + SH*DK_;          // SS*64
    float* kct = vs  + SS*DK_;          // 64*KTP
    float* sc  = kct + DK_*KTP;         // SH*SS
    float* offs= sc + SH*SS;            // SS
    int h = blockIdx.x, b = blockIdx.y, z = blockIdx.z;
    int tid = threadIdx.x;
    int lane = tid & 31, warp = tid >> 5;
    int base = b*SS*DD + h*DK_;
    int q0 = z*SH;

    for (int idx = tid; idx < SS*DK_; idx += 512) {
        int s = idx >> 6, d = idx & 63;
        int gi = base + s*DD + d;
        vs[idx] = v[gi];
        bool kp = x[b*SS + s] > 0;
        float k2v = k2[gi];
        kct[d*KTP + s] = kp ? (k1[gi] + k2v) : k2v;
    }
    for (int idx = tid; idx < SH*DK_; idx += 512) {
        int s = idx >> 6, d = idx & 63;
        qs[idx] = q[base + (q0 + s)*DD + d];
    }
    if (tid < SS) offs[tid] = (x[b*SS + tid] > 0) ? 0.0f : -1e9f;
    __syncthreads();

    const float scale = 0.125f;
    for (int g = tid; g < SH*25; g += 512) {
        int qi = g / 25;
        int kg = (g - qi*25) * 4;
        const float* qp = qs + qi*DK_;
        float4 s1 = make_float4(0.f,0.f,0.f,0.f);
        #pragma unroll 8
        for (int d = 0; d < DK_; d++) {
            float qv = qp[d];
            float4 b1 = *(const float4*)(kct + d*KTP + kg);
            s1.x += qv*b1.x; s1.y += qv*b1.y; s1.z += qv*b1.z; s1.w += qv*b1.w;
        }
        float* sr = sc + qi*SS + kg;
        const float* op = offs + kg;
        sr[0] = s1.x*scale + op[0];
        sr[1] = s1.y*scale + op[1];
        sr[2] = s1.z*scale + op[2];
        sr[3] = s1.w*scale + op[3];
    }
    __syncthreads();

    for (int r = warp; r < SH; r += 16) {
        float* row = sc + r*SS;
        float mx = -1e30f;
        for (int c = lane; c < SS; c += 32) mx = fmaxf(mx, row[c]);
        #pragma unroll
        for (int o = 16; o > 0; o >>= 1) mx = fmaxf(mx, __shfl_xor_sync(0xffffffff, mx, o));
        float sum = 0.f;
        for (int c = lane; c < SS; c += 32) {
            float e = __expf(row[c] - mx);
            row[c] = e; sum += e;
        }
        #pragma unroll
        for (int o = 16; o > 0; o >>= 1) sum += __shfl_xor_sync(0xffffffff, sum, o);
        float inv = 1.0f / sum;
        const float* mlr = ml + (q0 + r)*SS;
        for (int c = lane; c < SS; c += 32) {
            float zz = mlr[c];
            float sg = 1.0f / (1.0f + __expf(-zz));
            row[c] *= inv * sg;
        }
    }
    __syncthreads();

    for (int o = tid; o < SH*16; o += 512) {
        int qi = o >> 4;
        int dg = (o & 15) * 4;
        const float* sr = sc + qi*SS;
        const float* vp = vs + dg;
        float4 a = make_float4(0.f,0.f,0.f,0.f);
        #pragma unroll 4
        for (int k = 0; k < SS; k++) {
            float p = sr[k];
            float4 vv = *(const float4*)(vp + k*DK_);
            a.x += p*vv.x; a.y += p*vv.y; a.z += p*vv.z; a.w += p*vv.w;
        }
        *(float4*)(ctx + base + (q0 + qi)*DD + dg) = a;
    }
}

// ---------------- host launcher ----------------
extern "C" void kernel_launch(void* const* d_in, const int* in_sizes, int n_in,
                              void* d_out, int out_size)
{
    (void)in_sizes; (void)n_in; (void)out_size;
    const int*   x         = (const int*)  d_in[0];
    const float* times     = (const float*)d_in[1];
    const float* token_emb = (const float*)d_in[2];
    const float* pos_emb   = (const float*)d_in[3];
    const float* sel_w     = (const float*)d_in[4];
    const float* sel_b     = (const float*)d_in[5];
    const float* time_w    = (const float*)d_in[6];
    const float* time_b    = (const float*)d_in[7];
    const float* per_w     = (const float*)d_in[8];
    const float* per_b     = (const float*)d_in[9];
    const float* Wq        = (const float*)d_in[10];
    const float* Wk        = (const float*)d_in[11];
    const float* Wt        = (const float*)d_in[12];
    const float* Wv        = (const float*)d_in[13];
    const float* Wo        = (const float*)d_in[14];
    const float* bq        = (const float*)d_in[15];
    const float* bk        = (const float*)d_in[16];
    const float* bt        = (const float*)d_in[17];
    const float* bv        = (const float*)d_in[18];
    const float* bo        = (const float*)d_in[19];
    const float* mask_log  = (const float*)d_in[20];
    const float* ln1_a     = (const float*)d_in[21];
    const float* ln1_b     = (const float*)d_in[22];
    const float* ln2_a     = (const float*)d_in[23];
    const float* ln2_b     = (const float*)d_in[24];
    const float* ffn_w1    = (const float*)d_in[25];
    const float* ffn_b1    = (const float*)d_in[26];
    const float* ffn_w2    = (const float*)d_in[27];
    const float* ffn_b2    = (const float*)d_in[28];
    const float* out_w     = (const float*)d_in[29];
    const float* out_b     = (const float*)d_in[30];
    float* out = (float*)d_out;

    float *ph,*ptemb,*phn,*pq,*pk1,*pk2,*pv,*pctx,*pffn;
    cudaGetSymbolAddress((void**)&ph,    g_h);
    cudaGetSymbolAddress((void**)&ptemb, g_temb);
    cudaGetSymbolAddress((void**)&phn,   g_hn);
    cudaGetSymbolAddress((void**)&pq,    g_q);
    cudaGetSymbolAddress((void**)&pk1,   g_k1);
    cudaGetSymbolAddress((void**)&pk2,   g_k2);
    cudaGetSymbolAddress((void**)&pv,    g_v);
    cudaGetSymbolAddress((void**)&pctx,  g_ctx);
    cudaGetSymbolAddress((void**)&pffn,  g_ffn);

    const int attn_smem = (SH*DK_ + SS*DK_ + DK_*KTP + SH*SS + SS)*(int)sizeof(float); // ~85.4 KB
    cudaFuncSetAttribute(attn_kernel, cudaFuncAttributeMaxDynamicSharedMemorySize, attn_smem);

    embed_kernel<<<MM, 256>>>(x, times, token_emb, pos_emb, sel_w, sel_b,
                              time_w, time_b, per_w, per_b);

    dim3 gF(8, 25);            // 128x128 tiles, N=1024
    dim3 gS(4, 50);            // 64x64 tiles, N=256
    dim3 gQKTV(2, 25, 4);
    for (int l = 0; l < LL; l++) {
        ln_kernel<<<MM, 256>>>(ph, ln1_a + l*DD, ln1_b + l*DD, phn);
        qktv_gemm<<<gQKTV, 256>>>(phn, ptemb,
                                  Wq + (size_t)l*DD*DD, Wk + (size_t)l*DD*DD,
                                  Wt + (size_t)l*DD*DD, Wv + (size_t)l*DD*DD,
                                  bq + l*DD, bk + l*DD, bt + l*DD, bv + l*DD,
                                  pq, pk1, pk2, pv);
        attn_kernel<<<dim3(HH, BB, 2), 512, attn_smem>>>(pq, pk1, pk2, pv, x,
                                                         mask_log + l*SS*SS, pctx);
        gemm_s<<<gS, 128>>>(pctx, Wo + (size_t)l*DD*DD, bo + l*DD, ph, ph, DD, DD, 2);
        ln_kernel<<<MM, 256>>>(ph, ln2_a + l*DD, ln2_b + l*DD, phn);
        gemm_mma<<<gF, 256>>>(phn, ffn_w1 + (size_t)l*DFF_*DD, ffn_b1 + l*DFF_,
                              nullptr, pffn, DFF_, DD, 1);
        gemm_s<<<gS, 128>>>(pffn, ffn_w2 + (size_t)l*DD*DFF_, ffn_b2 + l*DD, ph, ph, DD, DFF_, 2);
    }
    gemm_mma<<<dim3(391, 25), 256>>>(ph, out_w, out_b, nullptr, out, NOUT, DD, 0);
}

// round 11
// speedup vs baseline: 2.0394x; 1.4055x over previous
#include <cuda_runtime.h>
#include <cuda_fp16.h>
#include <math.h>
#include <stdint.h>

// Problem constants
#define BB   32
#define SS   100
#define SH   50        // q rows per attention block (split 2)
#define DD   256
#define HH   4
#define DK_  64
#define LL   3
#define MM   (BB*SS)      // 3200
#define DFF_ 1024
#define NOUT 50001

// ---------------- scratch (no allocation allowed -> device globals) ----------------
__device__ float g_h[MM*DD];
__device__ float g_temb[MM*DD];
__device__ float g_hn[MM*DD];
__device__ float g_q[MM*DD];
__device__ float g_k1[MM*DD];
__device__ float g_k2[MM*DD];
__device__ float g_v[MM*DD];
__device__ float g_ctx[MM*DD];
__device__ float g_ffn[MM*DFF_];

// ---------------- embedding + time embedding ----------------
__global__ void embed_kernel(const int* __restrict__ x, const float* __restrict__ times,
                             const float* __restrict__ token_emb, const float* __restrict__ pos_emb,
                             const float* __restrict__ sel_w, const float* __restrict__ sel_b,
                             const float* __restrict__ time_w, const float* __restrict__ time_b,
                             const float* __restrict__ per_w, const float* __restrict__ per_b)
{
    int bs = blockIdx.x;
    int s  = bs % SS;
    int d  = threadIdx.x;
    __shared__ float g[64];
    float tval = times[bs];
    if (d < 64) {
        float t = tval * (1.0f/180.0f) * sel_w[d] + sel_b[d];
        g[d] = 1.0f - tanhf(t*t);
    }
    __syncthreads();
    float ang = 2.0f * 3.14159265358979323846f * tval / 24.0f;
    float sa = sinf(ang), ca = cosf(ang);
    float feat = time_b[d];
    const float* tw = time_w + d*64;
    #pragma unroll 16
    for (int j = 0; j < 64; j++) feat += g[j] * tw[j];
    float per = sa*per_w[d*2+0] + ca*per_w[d*2+1] + per_b[d];
    g_temb[bs*DD + d] = feat + per;
    int tok = x[bs];
    g_h[bs*DD + d] = token_emb[(size_t)tok*DD + d] + pos_emb[s*DD + d];
}

// ---------------- LayerNorm (torch variant: unbiased std, eps added to std) ----------------
__global__ void ln_kernel(const float* __restrict__ x, const float* __restrict__ a,
                          const float* __restrict__ b, float* __restrict__ y)
{
    int row = blockIdx.x;
    int d = threadIdx.x;
    int lane = d & 31, warp = d >> 5;
    __shared__ float ws1[8], ws2[8];
    float v = x[row*DD + d];
    float s = v;
    #pragma unroll
    for (int o = 16; o > 0; o >>= 1) s += __shfl_xor_sync(0xffffffff, s, o);
    if (lane == 0) ws1[warp] = s;
    __syncthreads();
    float tot = 0.f;
    #pragma unroll
    for (int i = 0; i < 8; i++) tot += ws1[i];
    float mean = tot * (1.0f/DD);
    float diff = v - mean;
    float s2 = diff*diff;
    #pragma unroll
    for (int o = 16; o > 0; o >>= 1) s2 += __shfl_xor_sync(0xffffffff, s2, o);
    if (lane == 0) ws2[warp] = s2;
    __syncthreads();
    float tot2 = 0.f;
    #pragma unroll
    for (int i = 0; i < 8; i++) tot2 += ws2[i];
    float stdv = sqrtf(tot2 * (1.0f/(DD-1)));
    y[row*DD + d] = a[d]*diff/(stdv + 1e-6f) + b[d];
}

// ---------------- GELU ----------------
__device__ __forceinline__ float gelu_f(float x) {
    const float c = 0.7978845608028654f;   // sqrt(2/pi)
    float x3 = x*x*x;
    return 0.5f*x*(1.0f + tanhf(c*(x + 0.044715f*x3)));
}

__device__ __forceinline__ uint32_t f2h2(float a, float b) {
    __half2 h = __floats2half2_rn(a, b);
    return *reinterpret_cast<uint32_t*>(&h);
}

// ---------------- raw mma.m16n8k16 fp16 (fp32 accum) ----------------
// A frag (4 b32): a0=(r,k0k1) a1=(r+8,k0k1) a2=(r,k8k9) a3=(r+8,k8k9); r=lane>>2, k pair=(lane&3)*2
// B frag (2 b32): b0=(k0k1,n)  b1=(k8k9,n); n=lane>>2
// C frag (4 f32): (r,2c) (r,2c+1) (r+8,2c) (r+8,2c+1); c=lane&3
__device__ __forceinline__ void mma16(float* c, const uint32_t* a, const uint32_t* b) {
    asm volatile("mma.sync.aligned.m16n8k16.row.col.f32.f16.f16.f32 "
        "{%0,%1,%2,%3}, {%4,%5,%6,%7}, {%8,%9}, {%0,%1,%2,%3};"
        : "+f"(c[0]), "+f"(c[1]), "+f"(c[2]), "+f"(c[3])
        : "r"(a[0]), "r"(a[1]), "r"(a[2]), "r"(a[3]), "r"(b[0]), "r"(b[1]));
}

// smem layouts (b32 units), per BK=16 k-chunk:
//   A: [t(m16 block)][lane][4]   block stride 128;  element (rp,c): lane=(rp&7)*4+((c&7)>>1), reg=(rp>>3)+(c>=8)*2
//   B: [u(n8 block)][lane][2]    block stride 64;   element (np,k): lane=np*4+((k&7)>>1),     reg=(k>=8)
// Loader thread (row lrow, k-half sK(8 floats)) -> A: base aoff = t*128+(rp&7)*16+(rp>>3)+sK*2, stride 4
//                                                  B: base boff = u*64+np*8+sK,               stride 2

// ---------------- GEMM v1: 128x128 tile, 8 warps (2Mx4N), warp 64x32, BK=16, double buffered ----
__device__ __forceinline__ void gemm_mma_body(const float* __restrict__ A,
                                              const float* __restrict__ W,
                                              const float* __restrict__ bias,
                                              const float* __restrict__ res,
                                              float* __restrict__ C,
                                              int N, int K, int row0, int col0, int epi)
{
    __shared__ uint32_t As[2][1024];
    __shared__ uint32_t Bs[2][1024];
    int tid = threadIdx.x;
    int warp = tid >> 5, lane = tid & 31;
    int wm = warp & 1, wn = warp >> 1;

    float acc[4][4][4];
    #pragma unroll
    for (int i = 0; i < 4; i++)
        #pragma unroll
        for (int j = 0; j < 4; j++)
            #pragma unroll
            for (int q = 0; q < 4; q++) acc[i][j][q] = 0.f;

    int lrow = tid >> 1;
    int sK   = tid & 1;
    const float* Ag = A + (size_t)(row0 + lrow)*K + sK*8;
    int wrow = col0 + lrow;
    const float* Wg = W + (size_t)wrow*K + sK*8;
    bool wv = wrow < N;

    int t = lrow >> 4, rp = lrow & 15;
    int aoff = t*128 + (rp & 7)*16 + (rp >> 3) + sK*2;
    int u = lrow >> 3, np = lrow & 7;
    int boff = u*64 + np*8 + sK;
    const float4 z4 = make_float4(0.f,0.f,0.f,0.f);

    {
        float4 a0 = *(const float4*)(Ag);
        float4 a1 = *(const float4*)(Ag + 4);
        float4 w0 = wv ? *(const float4*)(Wg)     : z4;
        float4 w1 = wv ? *(const float4*)(Wg + 4) : z4;
        uint32_t* ab = &As[0][aoff];
        ab[0]=f2h2(a0.x,a0.y); ab[4]=f2h2(a0.z,a0.w); ab[8]=f2h2(a1.x,a1.y); ab[12]=f2h2(a1.z,a1.w);
        uint32_t* bb = &Bs[0][boff];
        bb[0]=f2h2(w0.x,w0.y); bb[2]=f2h2(w0.z,w0.w); bb[4]=f2h2(w1.x,w1.y); bb[6]=f2h2(w1.z,w1.w);
    }
    __syncthreads();

    int buf = 0;
    for (int kk = 16; kk <= K; kk += 16) {
        float4 na0, na1, nw0, nw1;
        bool more = (kk < K);
        if (more) {
            na0 = *(const float4*)(Ag + kk);
            na1 = *(const float4*)(Ag + kk + 4);
            nw0 = wv ? *(const float4*)(Wg + kk)     : z4;
            nw1 = wv ? *(const float4*)(Wg + kk + 4) : z4;
        }
        const uint32_t* Ab = As[buf];
        const uint32_t* Bb = Bs[buf];
        uint32_t af[4][4], bf[4][2];
        #pragma unroll
        for (int i = 0; i < 4; i++) {
            uint4 v = *(const uint4*)(Ab + (wm*4 + i)*128 + lane*4);
            af[i][0] = v.x; af[i][1] = v.y; af[i][2] = v.z; af[i][3] = v.w;
        }
        #pragma unroll
        for (int j = 0; j < 4; j++) {
            uint2 v = *(const uint2*)(Bb + (wn*4 + j)*64 + lane*2);
            bf[j][0] = v.x; bf[j][1] = v.y;
        }
        #pragma unroll
        for (int i = 0; i < 4; i++)
            #pragma unroll
            for (int j = 0; j < 4; j++)
                mma16(acc[i][j], af[i], bf[j]);
        if (more) {
            uint32_t* ab = &As[buf^1][aoff];
            ab[0]=f2h2(na0.x,na0.y); ab[4]=f2h2(na0.z,na0.w); ab[8]=f2h2(na1.x,na1.y); ab[12]=f2h2(na1.z,na1.w);
            uint32_t* bb = &Bs[buf^1][boff];
            bb[0]=f2h2(nw0.x,nw0.y); bb[2]=f2h2(nw0.z,nw0.w); bb[4]=f2h2(nw1.x,nw1.y); bb[6]=f2h2(nw1.z,nw1.w);
            __syncthreads();
            buf ^= 1;
        }
    }

    int r = lane >> 2, c2 = (lane & 3) * 2;
    #pragma unroll
    for (int i = 0; i < 4; i++) {
        int gr = row0 + wm*64 + i*16 + r;
        size_t rb0 = (size_t)gr * N;
        size_t rb1 = (size_t)(gr + 8) * N;
        #pragma unroll
        for (int j = 0; j < 4; j++) {
            int gc = col0 + wn*32 + j*8 + c2;
            const float* cp = acc[i][j];
            if (gc + 1 < N) {
                float b0 = bias[gc], b1 = bias[gc+1];
                float v0 = cp[0] + b0, v1 = cp[1] + b1;
                float v2 = cp[2] + b0, v3 = cp[3] + b1;
                if (epi == 1) { v0 = gelu_f(v0); v1 = gelu_f(v1); v2 = gelu_f(v2); v3 = gelu_f(v3); }
                else if (epi == 2) {
                    v0 += res[rb0 + gc]; v1 += res[rb0 + gc + 1];
                    v2 += res[rb1 + gc]; v3 += res[rb1 + gc + 1];
                }
                C[rb0 + gc] = v0; C[rb0 + gc + 1] = v1;
                C[rb1 + gc] = v2; C[rb1 + gc + 1] = v3;
            } else if (gc < N) {
                float b0 = bias[gc];
                float v0 = cp[0] + b0, v2 = cp[2] + b0;
                if (epi == 1) { v0 = gelu_f(v0); v2 = gelu_f(v2); }
                else if (epi == 2) { v0 += res[rb0 + gc]; v2 += res[rb1 + gc]; }
                C[rb0 + gc] = v0; C[rb1 + gc] = v2;
            }
        }
    }
}

__global__ void __launch_bounds__(256, 2) gemm_mma(const float* __restrict__ A,
                                                   const float* __restrict__ W,
                                                   const float* __restrict__ bias,
                                                   const float* __restrict__ res,
                                                   float* __restrict__ C, int N, int K, int epi)
{
    gemm_mma_body(A, W, bias, res, C, N, K, blockIdx.y*128, blockIdx.x*128, epi);
}

__global__ void __launch_bounds__(256, 2) qktv_gemm(const float* __restrict__ hn,
                                                    const float* __restrict__ temb,
                                                    const float* __restrict__ Wq, const float* __restrict__ Wk,
                                                    const float* __restrict__ Wt, const float* __restrict__ Wv,
                                                    const float* __restrict__ bq, const float* __restrict__ bk,
                                                    const float* __restrict__ bt, const float* __restrict__ bv,
                                                    float* __restrict__ q, float* __restrict__ k1,
                                                    float* __restrict__ k2, float* __restrict__ v)
{
    int z = blockIdx.z;
    const float* A = (z == 2) ? temb : hn;
    const float* W = (z == 0) ? Wq : (z == 1) ? Wk : (z == 2) ? Wt : Wv;
    const float* b = (z == 0) ? bq : (z == 1) ? bk : (z == 2) ? bt : bv;
    float*       C = (z == 0) ? q  : (z == 1) ? k1 : (z == 2) ? k2 : v;
    gemm_mma_body(A, W, b, nullptr, C, DD, DD, blockIdx.y*128, blockIdx.x*128, 0);
}

// ---------------- GEMM small: 64x64 tile, 4 warps (2Mx2N), warp 32x32, BK=16, double buffered ----
__global__ void __launch_bounds__(128) gemm_s(const float* __restrict__ A,
                                              const float* __restrict__ W,
                                              const float* __restrict__ bias,
                                              const float* __restrict__ res,
                                              float* __restrict__ C, int N, int K, int epi)
{
    __shared__ uint32_t As[2][512];
    __shared__ uint32_t Bs[2][512];
    int tid = threadIdx.x;
    int warp = tid >> 5, lane = tid & 31;
    int wm = warp & 1, wn = warp >> 1;
    int row0 = blockIdx.y*64, col0 = blockIdx.x*64;

    float acc[2][4][4];
    #pragma unroll
    for (int i = 0; i < 2; i++)
        #pragma unroll
        for (int j = 0; j < 4; j++)
            #pragma unroll
            for (int q = 0; q < 4; q++) acc[i][j][q] = 0.f;

    int lrow = tid >> 1;          // 0..63
    int sK   = tid & 1;
    const float* Ag = A + (size_t)(row0 + lrow)*K + sK*8;
    int wrow = col0 + lrow;
    const float* Wg = W + (size_t)wrow*K + sK*8;
    bool wv = wrow < N;

    int t = lrow >> 4, rp = lrow & 15;        // t: 0..3
    int aoff = t*128 + (rp & 7)*16 + (rp >> 3) + sK*2;
    int u = lrow >> 3, np = lrow & 7;         // u: 0..7
    int boff = u*64 + np*8 + sK;
    const float4 z4 = make_float4(0.f,0.f,0.f,0.f);

    {
        float4 a0 = *(const float4*)(Ag);
        float4 a1 = *(const float4*)(Ag + 4);
        float4 w0 = wv ? *(const float4*)(Wg)     : z4;
        float4 w1 = wv ? *(const float4*)(Wg + 4) : z4;
        uint32_t* ab = &As[0][aoff];
        ab[0]=f2h2(a0.x,a0.y); ab[4]=f2h2(a0.z,a0.w); ab[8]=f2h2(a1.x,a1.y); ab[12]=f2h2(a1.z,a1.w);
        uint32_t* bb = &Bs[0][boff];
        bb[0]=f2h2(w0.x,w0.y); bb[2]=f2h2(w0.z,w0.w); bb[4]=f2h2(w1.x,w1.y); bb[6]=f2h2(w1.z,w1.w);
    }
    __syncthreads();

    int buf = 0;
    for (int kk = 16; kk <= K; kk += 16) {
        float4 na0, na1, nw0, nw1;
        bool more = (kk < K);
        if (more) {
            na0 = *(const float4*)(Ag + kk);
            na1 = *(const float4*)(Ag + kk + 4);
            nw0 = wv ? *(const float4*)(Wg + kk)     : z4;
            nw1 = wv ? *(const float4*)(Wg + kk + 4) : z4;
        }
        const uint32_t* Ab = As[buf];
        const uint32_t* Bb = Bs[buf];
        uint32_t af[2][4], bf[4][2];
        #pragma unroll
        for (int i = 0; i < 2; i++) {
            uint4 v = *(const uint4*)(Ab + (wm*2 + i)*128 + lane*4);
            af[i][0] = v.x; af[i][1] = v.y; af[i][2] = v.z; af[i][3] = v.w;
        }
        #pragma unroll
        for (int j = 0; j < 4; j++) {
            uint2 v = *(const uint2*)(Bb + (wn*4 + j)*64 + lane*2);
            bf[j][0] = v.x; bf[j][1] = v.y;
        }
        #pragma unroll
        for (int i = 0; i < 2; i++)
            #pragma unroll
            for (int j = 0; j < 4; j++)
                mma16(acc[i][j], af[i], bf[j]);
        if (more) {
            uint32_t* ab = &As[buf^1][aoff];
            ab[0]=f2h2(na0.x,na0.y); ab[4]=f2h2(na0.z,na0.w); ab[8]=f2h2(na1.x,na1.y); ab[12]=f2h2(na1.z,na1.w);
            uint32_t* bb = &Bs[buf^1][boff];
            bb[0]=f2h2(nw0.x,nw0.y); bb[2]=f2h2(nw0.z,nw0.w); bb[4]=f2h2(nw1.x,nw1.y); bb[6]=f2h2(nw1.z,nw1.w);
            __syncthreads();
            buf ^= 1;
        }
    }

    int r = lane >> 2, c2 = (lane & 3) * 2;
    #pragma unroll
    for (int i = 0; i < 2; i++) {
        int gr = row0 + wm*32 + i*16 + r;
        size_t rb0 = (size_t)gr * N;
        size_t rb1 = (size_t)(gr + 8) * N;
        #pragma unroll
        for (int j = 0; j < 4; j++) {
            int gc = col0 + wn*32 + j*8 + c2;
            const float* cp = acc[i][j];
            if (gc + 1 < N) {
                float b0 = bias[gc], b1 = bias[gc+1];
                float v0 = cp[0] + b0, v1 = cp[1] + b1;
                float v2 = cp[2] + b0, v3 = cp[3] + b1;
                if (epi == 1) { v0 = gelu_f(v0); v1 = gelu_f(v1); v2 = gelu_f(v2); v3 = gelu_f(v3); }
                else if (epi == 2) {
                    v0 += res[rb0 + gc]; v1 += res[rb0 + gc + 1];
                    v2 += res[rb1 + gc]; v3 += res[rb1 + gc + 1];
                }
                C[rb0 + gc] = v0; C[rb0 + gc + 1] = v1;
                C[rb1 + gc] = v2; C[rb1 + gc + 1] = v3;
            } else if (gc < N) {
                float b0 = bias[gc];
                float v0 = cp[0] + b0, v2 = cp[2] + b0;
                if (epi == 1) { v0 = gelu_f(v0); v2 = gelu_f(v2); }
                else if (epi == 2) { v0 += res[rb0 + gc]; v2 += res[rb1 + gc]; }
                C[rb0 + gc] = v0; C[rb1 + gc] = v2;
            }
        }
    }
}

// ---------------- attention: grid (H, B, 2) -- each block does 50 query rows ----------------
#define KTP 104

__global__ void __launch_bounds__(512) attn_kernel(
        const float* __restrict__ q, const float* __restrict__ k1,
        const float* __restrict__ k2, const float* __restrict__ v,
        const int* __restrict__ x, const float* __restrict__ ml,
        float* __restrict__ ctx)
{
    extern __shared__ float sm[];
    float* qs  = sm;                    // SH*64
    float* vs  = qs  + SH*DK_;          // SS*64
    float* kct = vs  + SS*DK_;          // 64*KTP
    float* sc  = kct + DK_*KTP;         // SH*SS
    float* offs= sc + SH*SS;            // SS
    int h = blockIdx.x, b = blockIdx.y, z = blockIdx.z;
    int tid = threadIdx.x;
    int lane = tid & 31, warp = tid >> 5;
    int base = b*SS*DD + h*DK_;
    int q0 = z*SH;

    for (int idx = tid; idx < SS*DK_; idx += 512) {
        int s = idx >> 6, d = idx & 63;
        int gi = base + s*DD + d;
        vs[idx] = v[gi];
        bool kp = x[b*SS + s] > 0;
        float k2v = k2[gi];
        kct[d*KTP + s] = kp ? (k1[gi] + k2v) : k2v;
    }
    for (int idx = tid; idx < SH*DK_; idx += 512) {
        int s = idx >> 6, d = idx & 63;
        qs[idx] = q[base + (q0 + s)*DD + d];
    }
    if (tid < SS) offs[tid] = (x[b*SS + tid] > 0) ? 0.0f : -1e9f;
    __syncthreads();

    const float scale = 0.125f;
    for (int g = tid; g < SH*25; g += 512) {
        int qi = g / 25;
        int kg = (g - qi*25) * 4;
        const float* qp = qs + qi*DK_;
        float4 s1 = make_float4(0.f,0.f,0.f,0.f);
        #pragma unroll 8
        for (int d = 0; d < DK_; d++) {
            float qv = qp[d];
            float4 b1 = *(const float4*)(kct + d*KTP + kg);
            s1.x += qv*b1.x; s1.y += qv*b1.y; s1.z += qv*b1.z; s1.w += qv*b1.w;
        }
        float* sr = sc + qi*SS + kg;
        const float* op = offs + kg;
        sr[0] = s1.x*scale + op[0];
        sr[1] = s1.y*scale + op[1];
        sr[2] = s1.z*scale + op[2];
        sr[3] = s1.w*scale + op[3];
    }
    __syncthreads();

    for (int r = warp; r < SH; r += 16) {
        float* row = sc + r*SS;
        float mx = -1e30f;
        for (int c = lane; c < SS; c += 32) mx = fmaxf(mx, row[c]);
        #pragma unroll
        for (int o = 16; o > 0; o >>= 1) mx = fmaxf(mx, __shfl_xor_sync(0xffffffff, mx, o));
        float sum = 0.f;
        for (int c = lane; c < SS; c += 32) {
            float e = __expf(row[c] - mx);
            row[c] = e; sum += e;
        }
        #pragma unroll
        for (int o = 16; o > 0; o >>= 1) sum += __shfl_xor_sync(0xffffffff, sum, o);
        float inv = 1.0f / sum;
        const float* mlr = ml + (q0 + r)*SS;
        for (int c = lane; c < SS; c += 32) {
            float zz = mlr[c];
            float sg = 1.0f / (1.0f + __expf(-zz));
            row[c] *= inv * sg;
        }
    }
    __syncthreads();

    for (int o = tid; o < SH*16; o += 512) {
        int qi = o >> 4;
        int dg = (o & 15) * 4;
        const float* sr = sc + qi*SS;
        const float* vp = vs + dg;
        float4 a = make_float4(0.f,0.f,0.f,0.f);
        #pragma unroll 4
        for (int k = 0; k < SS; k++) {
            float p = sr[k];
            float4 vv = *(const float4*)(vp + k*DK_);
            a.x += p*vv.x; a.y += p*vv.y; a.z += p*vv.z; a.w += p*vv.w;
        }
        *(float4*)(ctx + base + (q0 + qi)*DD + dg) = a;
    }
}

// ---------------- host launcher ----------------
extern "C" void kernel_launch(void* const* d_in, const int* in_sizes, int n_in,
                              void* d_out, int out_size)
{
    (void)in_sizes; (void)n_in; (void)out_size;
    const int*   x         = (const int*)  d_in[0];
    const float* times     = (const float*)d_in[1];
    const float* token_emb = (const float*)d_in[2];
    const float* pos_emb   = (const float*)d_in[3];
    const float* sel_w     = (const float*)d_in[4];
    const float* sel_b     = (const float*)d_in[5];
    const float* time_w    = (const float*)d_in[6];
    const float* time_b    = (const float*)d_in[7];
    const float* per_w     = (const float*)d_in[8];
    const float* per_b     = (const float*)d_in[9];
    const float* Wq        = (const float*)d_in[10];
    const float* Wk        = (const float*)d_in[11];
    const float* Wt        = (const float*)d_in[12];
    const float* Wv        = (const float*)d_in[13];
    const float* Wo        = (const float*)d_in[14];
    const float* bq        = (const float*)d_in[15];
    const float* bk        = (const float*)d_in[16];
    const float* bt        = (const float*)d_in[17];
    const float* bv        = (const float*)d_in[18];
    const float* bo        = (const float*)d_in[19];
    const float* mask_log  = (const float*)d_in[20];
    const float* ln1_a     = (const float*)d_in[21];
    const float* ln1_b     = (const float*)d_in[22];
    const float* ln2_a     = (const float*)d_in[23];
    const float* ln2_b     = (const float*)d_in[24];
    const float* ffn_w1    = (const float*)d_in[25];
    const float* ffn_b1    = (const float*)d_in[26];
    const float* ffn_w2    = (const float*)d_in[27];
    const float* ffn_b2    = (const float*)d_in[28];
    const float* out_w     = (const float*)d_in[29];
    const float* out_b     = (const float*)d_in[30];
    float* out = (float*)d_out;

    float *ph,*ptemb,*phn,*pq,*pk1,*pk2,*pv,*pctx,*pffn;
    cudaGetSymbolAddress((void**)&ph,    g_h);
    cudaGetSymbolAddress((void**)&ptemb, g_temb);
    cudaGetSymbolAddress((void**)&phn,   g_hn);
    cudaGetSymbolAddress((void**)&pq,    g_q);
    cudaGetSymbolAddress((void**)&pk1,   g_k1);
    cudaGetSymbolAddress((void**)&pk2,   g_k2);
    cudaGetSymbolAddress((void**)&pv,    g_v);
    cudaGetSymbolAddress((void**)&pctx,  g_ctx);
    cudaGetSymbolAddress((void**)&pffn,  g_ffn);

    const int attn_smem = (SH*DK_ + SS*DK_ + DK_*KTP + SH*SS + SS)*(int)sizeof(float); // ~85.4 KB
    cudaFuncSetAttribute(attn_kernel, cudaFuncAttributeMaxDynamicSharedMemorySize, attn_smem);

    embed_kernel<<<MM, 256>>>(x, times, token_emb, pos_emb, sel_w, sel_b,
                              time_w, time_b, per_w, per_b);

    dim3 gF(8, 25);            // 128x128 tiles, N=1024
    dim3 gS(4, 50);            // 64x64 tiles, N=256
    dim3 gQKTV(2, 25, 4);
    for (int l = 0; l < LL; l++) {
        ln_kernel<<<MM, 256>>>(ph, ln1_a + l*DD, ln1_b + l*DD, phn);
        qktv_gemm<<<gQKTV, 256>>>(phn, ptemb,
                                  Wq + (size_t)l*DD*DD, Wk + (size_t)l*DD*DD,
                                  Wt + (size_t)l*DD*DD, Wv + (size_t)l*DD*DD,
                                  bq + l*DD, bk + l*DD, bt + l*DD, bv + l*DD,
                                  pq, pk1, pk2, pv);
        attn_kernel<<<dim3(HH, BB, 2), 512, attn_smem>>>(pq, pk1, pk2, pv, x,
                                                         mask_log + l*SS*SS, pctx);
        gemm_s<<<gS, 128>>>(pctx, Wo + (size_t)l*DD*DD, bo + l*DD, ph, ph, DD, DD, 2);
        ln_kernel<<<MM, 256>>>(ph, ln2_a + l*DD, ln2_b + l*DD, phn);
        gemm_mma<<<gF, 256>>>(phn, ffn_w1 + (size_t)l*DFF_*DD, ffn_b1 + l*DFF_,
                              nullptr, pffn, DFF_, DD, 1);
        gemm_s<<<gS, 128>>>(pffn, ffn_w2 + (size_t)l*DD*DFF_, ffn_b2 + l*DD, ph, ph, DD, DFF_, 2);
    }
    gemm_mma<<<dim3(391, 25), 256>>>(ph, out_w, out_b, nullptr, out, NOUT, DD, 0);
}

// round 12
// speedup vs baseline: 2.4351x; 1.1940x over previous
#include <cuda_runtime.h>
#include <cuda_fp16.h>
#include <math.h>
#include <stdint.h>

// Problem constants
#define BB   32
#define SS   100
#define SH   50        // q rows per attention block (split 2)
#define DD   256
#define HH   4
#define DK_  64
#define LL   3
#define MM   (BB*SS)      // 3200
#define DFF_ 1024
#define NOUT 50001

// ---------------- scratch (no allocation allowed -> device globals) ----------------
__device__ float g_h[MM*DD];
__device__ float g_q[MM*DD];
__device__ float g_k1[MM*DD];
__device__ float g_k2[MM*DD];
__device__ float g_v[MM*DD];
// fp16 operand network
__device__ __align__(16) __half g_hn_h[MM*DD];
__device__ __align__(16) __half g_temb_h[MM*DD];
__device__ __align__(16) __half g_ctx_h[MM*DD];
__device__ __align__(16) __half g_ffn_h[MM*DFF_];
__device__ __align__(16) __half g_hh[MM*DD];
// fp16 weights
__device__ __align__(16) __half g_Wqh[LL*DD*DD];
__device__ __align__(16) __half g_Wkh[LL*DD*DD];
__device__ __align__(16) __half g_Wth[LL*DD*DD];
__device__ __align__(16) __half g_Wvh[LL*DD*DD];
__device__ __align__(16) __half g_Woh[LL*DD*DD];
__device__ __align__(16) __half g_w1h[LL*DFF_*DD];
__device__ __align__(16) __half g_w2h[LL*DD*DFF_];
__device__ __align__(16) __half g_outwh[(size_t)NOUT*DD];

// ---------------- fp32 -> fp16 convert ----------------
__global__ void f2h_kernel(const float* __restrict__ src, __half* __restrict__ dst, int n4) {
    int i = blockIdx.x*blockDim.x + threadIdx.x;
    if (i < n4) {
        float4 v = ((const float4*)src)[i];
        ((__half2*)dst)[i*2]   = __floats2half2_rn(v.x, v.y);
        ((__half2*)dst)[i*2+1] = __floats2half2_rn(v.z, v.w);
    }
}

// ---------------- embedding + time embedding ----------------
__global__ void embed_kernel(const int* __restrict__ x, const float* __restrict__ times,
                             const float* __restrict__ token_emb, const float* __restrict__ pos_emb,
                             const float* __restrict__ sel_w, const float* __restrict__ sel_b,
                             const float* __restrict__ time_w, const float* __restrict__ time_b,
                             const float* __restrict__ per_w, const float* __restrict__ per_b)
{
    int bs = blockIdx.x;
    int s  = bs % SS;
    int d  = threadIdx.x;
    __shared__ float g[64];
    float tval = times[bs];
    if (d < 64) {
        float t = tval * (1.0f/180.0f) * sel_w[d] + sel_b[d];
        g[d] = 1.0f - tanhf(t*t);
    }
    __syncthreads();
    float ang = 2.0f * 3.14159265358979323846f * tval / 24.0f;
    float sa = sinf(ang), ca = cosf(ang);
    float feat = time_b[d];
    const float* tw = time_w + d*64;
    #pragma unroll 16
    for (int j = 0; j < 64; j++) feat += g[j] * tw[j];
    float per = sa*per_w[d*2+0] + ca*per_w[d*2+1] + per_b[d];
    g_temb_h[bs*DD + d] = __float2half(feat + per);
    int tok = x[bs];
    g_h[bs*DD + d] = token_emb[(size_t)tok*DD + d] + pos_emb[s*DD + d];
}

// ---------------- LayerNorm (torch variant) -> half output ----------------
__global__ void ln_kernel(const float* __restrict__ x, const float* __restrict__ a,
                          const float* __restrict__ b, __half* __restrict__ y)
{
    int row = blockIdx.x;
    int d = threadIdx.x;
    int lane = d & 31, warp = d >> 5;
    __shared__ float ws1[8], ws2[8];
    float v = x[row*DD + d];
    float s = v;
    #pragma unroll
    for (int o = 16; o > 0; o >>= 1) s += __shfl_xor_sync(0xffffffff, s, o);
    if (lane == 0) ws1[warp] = s;
    __syncthreads();
    float tot = 0.f;
    #pragma unroll
    for (int i = 0; i < 8; i++) tot += ws1[i];
    float mean = tot * (1.0f/DD);
    float diff = v - mean;
    float s2 = diff*diff;
    #pragma unroll
    for (int o = 16; o > 0; o >>= 1) s2 += __shfl_xor_sync(0xffffffff, s2, o);
    if (lane == 0) ws2[warp] = s2;
    __syncthreads();
    float tot2 = 0.f;
    #pragma unroll
    for (int i = 0; i < 8; i++) tot2 += ws2[i];
    float stdv = sqrtf(tot2 * (1.0f/(DD-1)));
    y[row*DD + d] = __float2half(a[d]*diff/(stdv + 1e-6f) + b[d]);
}

// ---------------- GELU ----------------
__device__ __forceinline__ float gelu_f(float x) {
    const float c = 0.7978845608028654f;   // sqrt(2/pi)
    float x3 = x*x*x;
    return 0.5f*x*(1.0f + tanhf(c*(x + 0.044715f*x3)));
}

// ---------------- raw mma.m16n8k16 fp16 (fp32 accum) ----------------
__device__ __forceinline__ void mma16(float* c, const uint32_t* a, const uint32_t* b) {
    asm volatile("mma.sync.aligned.m16n8k16.row.col.f32.f16.f16.f32 "
        "{%0,%1,%2,%3}, {%4,%5,%6,%7}, {%8,%9}, {%0,%1,%2,%3};"
        : "+f"(c[0]), "+f"(c[1]), "+f"(c[2]), "+f"(c[3])
        : "r"(a[0]), "r"(a[1]), "r"(a[2]), "r"(a[3]), "r"(b[0]), "r"(b[1]));
}

// ---------------- GEMM v1: 128x128 tile, 8 warps (2Mx4N), warp 64x32, BK=16, double buffered ----
// epi: 0 = C fp32; 1 = Ch = half(gelu); 2 = C fp32 += res; 3 = C fp32 += res AND Ch = half(C)
__device__ __forceinline__ void gemm_mma_body(const __half* __restrict__ A,
                                              const __half* __restrict__ W,
                                              const float* __restrict__ bias,
                                              const float* __restrict__ res,
                                              float* __restrict__ C,
                                              __half* __restrict__ Ch,
                                              int N, int K, int row0, int col0, int epi)
{
    __shared__ uint32_t As[2][1024];
    __shared__ uint32_t Bs[2][1024];
    int tid = threadIdx.x;
    int warp = tid >> 5, lane = tid & 31;
    int wm = warp & 1, wn = warp >> 1;

    float acc[4][4][4];
    #pragma unroll
    for (int i = 0; i < 4; i++)
        #pragma unroll
        for (int j = 0; j < 4; j++)
            #pragma unroll
            for (int q = 0; q < 4; q++) acc[i][j][q] = 0.f;

    int lrow = tid >> 1;
    int sK   = tid & 1;
    const __half* Ag = A + (size_t)(row0 + lrow)*K + sK*8;
    int wrow = col0 + lrow;
    const __half* Wg = W + (size_t)wrow*K + sK*8;
    bool wv = wrow < N;

    int t = lrow >> 4, rp = lrow & 15;
    int aoff = t*128 + (rp & 7)*16 + (rp >> 3) + sK*2;
    int u = lrow >> 3, np = lrow & 7;
    int boff = u*64 + np*8 + sK;
    const uint4 z4 = make_uint4(0u,0u,0u,0u);

    {
        uint4 a = *(const uint4*)(Ag);
        uint4 w = wv ? *(const uint4*)(Wg) : z4;
        uint32_t* ab = &As[0][aoff];
        ab[0]=a.x; ab[4]=a.y; ab[8]=a.z; ab[12]=a.w;
        uint32_t* bb = &Bs[0][boff];
        bb[0]=w.x; bb[2]=w.y; bb[4]=w.z; bb[6]=w.w;
    }
    __syncthreads();

    int buf = 0;
    for (int kk = 16; kk <= K; kk += 16) {
        uint4 na, nw;
        bool more = (kk < K);
        if (more) {
            na = *(const uint4*)(Ag + kk);
            nw = wv ? *(const uint4*)(Wg + kk) : z4;
        }
        const uint32_t* Ab = As[buf];
        const uint32_t* Bb = Bs[buf];
        uint32_t af[4][4], bf[4][2];
        #pragma unroll
        for (int i = 0; i < 4; i++) {
            uint4 v = *(const uint4*)(Ab + (wm*4 + i)*128 + lane*4);
            af[i][0] = v.x; af[i][1] = v.y; af[i][2] = v.z; af[i][3] = v.w;
        }
        #pragma unroll
        for (int j = 0; j < 4; j++) {
            uint2 v = *(const uint2*)(Bb + (wn*4 + j)*64 + lane*2);
            bf[j][0] = v.x; bf[j][1] = v.y;
        }
        #pragma unroll
        for (int i = 0; i < 4; i++)
            #pragma unroll
            for (int j = 0; j < 4; j++)
                mma16(acc[i][j], af[i], bf[j]);
        if (more) {
            uint32_t* ab = &As[buf^1][aoff];
            ab[0]=na.x; ab[4]=na.y; ab[8]=na.z; ab[12]=na.w;
            uint32_t* bb = &Bs[buf^1][boff];
            bb[0]=nw.x; bb[2]=nw.y; bb[4]=nw.z; bb[6]=nw.w;
            __syncthreads();
            buf ^= 1;
        }
    }

    int r = lane >> 2, c2 = (lane & 3) * 2;
    #pragma unroll
    for (int i = 0; i < 4; i++) {
        int gr = row0 + wm*64 + i*16 + r;
        size_t rb0 = (size_t)gr * N;
        size_t rb1 = (size_t)(gr + 8) * N;
        #pragma unroll
        for (int j = 0; j < 4; j++) {
            int gc = col0 + wn*32 + j*8 + c2;
            const float* cp = acc[i][j];
            if (gc + 1 < N) {
                float b0 = bias[gc], b1 = bias[gc+1];
                float v0 = cp[0] + b0, v1 = cp[1] + b1;
                float v2 = cp[2] + b0, v3 = cp[3] + b1;
                if (epi == 0) {
                    C[rb0 + gc] = v0; C[rb0 + gc + 1] = v1;
                    C[rb1 + gc] = v2; C[rb1 + gc + 1] = v3;
                } else if (epi == 1) {
                    *(__half2*)(Ch + rb0 + gc) = __floats2half2_rn(gelu_f(v0), gelu_f(v1));
                    *(__half2*)(Ch + rb1 + gc) = __floats2half2_rn(gelu_f(v2), gelu_f(v3));
                } else {
                    v0 += res[rb0 + gc]; v1 += res[rb0 + gc + 1];
                    v2 += res[rb1 + gc]; v3 += res[rb1 + gc + 1];
                    C[rb0 + gc] = v0; C[rb0 + gc + 1] = v1;
                    C[rb1 + gc] = v2; C[rb1 + gc + 1] = v3;
                    if (epi == 3) {
                        *(__half2*)(Ch + rb0 + gc) = __floats2half2_rn(v0, v1);
                        *(__half2*)(Ch + rb1 + gc) = __floats2half2_rn(v2, v3);
                    }
                }
            } else if (gc < N) {
                float b0 = bias[gc];
                float v0 = cp[0] + b0, v2 = cp[2] + b0;
                if (epi == 0) {
                    C[rb0 + gc] = v0; C[rb1 + gc] = v2;
                } else if (epi == 1) {
                    Ch[rb0 + gc] = __float2half(gelu_f(v0));
                    Ch[rb1 + gc] = __float2half(gelu_f(v2));
                } else {
                    v0 += res[rb0 + gc]; v2 += res[rb1 + gc];
                    C[rb0 + gc] = v0; C[rb1 + gc] = v2;
                    if (epi == 3) {
                        Ch[rb0 + gc] = __float2half(v0);
                        Ch[rb1 + gc] = __float2half(v2);
                    }
                }
            }
        }
    }
}

__global__ void __launch_bounds__(256, 2) gemm_mma(const __half* __restrict__ A,
                                                   const __half* __restrict__ W,
                                                   const float* __restrict__ bias,
                                                   const float* __restrict__ res,
                                                   float* __restrict__ C,
                                                   __half* __restrict__ Ch,
                                                   int N, int K, int epi)
{
    gemm_mma_body(A, W, bias, res, C, Ch, N, K, blockIdx.y*128, blockIdx.x*128, epi);
}

__global__ void __launch_bounds__(256, 2) qktv_gemm(const __half* __restrict__ hn,
                                                    const __half* __restrict__ temb,
                                                    const __half* __restrict__ Wq, const __half* __restrict__ Wk,
                                                    const __half* __restrict__ Wt, const __half* __restrict__ Wv,
                                                    const float* __restrict__ bq, const float* __restrict__ bk,
                                                    const float* __restrict__ bt, const float* __restrict__ bv,
                                                    float* __restrict__ q, float* __restrict__ k1,
                                                    float* __restrict__ k2, float* __restrict__ v)
{
    int z = blockIdx.z;
    const __half* A = (z == 2) ? temb : hn;
    const __half* W = (z == 0) ? Wq : (z == 1) ? Wk : (z == 2) ? Wt : Wv;
    const float* b = (z == 0) ? bq : (z == 1) ? bk : (z == 2) ? bt : bv;
    float*       C = (z == 0) ? q  : (z == 1) ? k1 : (z == 2) ? k2 : v;
    gemm_mma_body(A, W, b, nullptr, C, nullptr, DD, DD, blockIdx.y*128, blockIdx.x*128, 0);
}

// ---------------- GEMM small: 64x64 tile, 4 warps (2Mx2N), warp 32x32, BK=16, double buffered ----
__global__ void __launch_bounds__(128) gemm_s(const __half* __restrict__ A,
                                              const __half* __restrict__ W,
                                              const float* __restrict__ bias,
                                              const float* __restrict__ res,
                                              float* __restrict__ C,
                                              __half* __restrict__ Ch,
                                              int N, int K, int epi)
{
    __shared__ uint32_t As[2][512];
    __shared__ uint32_t Bs[2][512];
    int tid = threadIdx.x;
    int warp = tid >> 5, lane = tid & 31;
    int wm = warp & 1, wn = warp >> 1;
    int row0 = blockIdx.y*64, col0 = blockIdx.x*64;

    float acc[2][4][4];
    #pragma unroll
    for (int i = 0; i < 2; i++)
        #pragma unroll
        for (int j = 0; j < 4; j++)
            #pragma unroll
            for (int q = 0; q < 4; q++) acc[i][j][q] = 0.f;

    int lrow = tid >> 1;          // 0..63
    int sK   = tid & 1;
    const __half* Ag = A + (size_t)(row0 + lrow)*K + sK*8;
    int wrow = col0 + lrow;
    const __half* Wg = W + (size_t)wrow*K + sK*8;
    bool wv = wrow < N;

    int t = lrow >> 4, rp = lrow & 15;        // t: 0..3
    int aoff = t*128 + (rp & 7)*16 + (rp >> 3) + sK*2;
    int u = lrow >> 3, np = lrow & 7;         // u: 0..7
    int boff = u*64 + np*8 + sK;
    const uint4 z4 = make_uint4(0u,0u,0u,0u);

    {
        uint4 a = *(const uint4*)(Ag);
        uint4 w = wv ? *(const uint4*)(Wg) : z4;
        uint32_t* ab = &As[0][aoff];
        ab[0]=a.x; ab[4]=a.y; ab[8]=a.z; ab[12]=a.w;
        uint32_t* bb = &Bs[0][boff];
        bb[0]=w.x; bb[2]=w.y; bb[4]=w.z; bb[6]=w.w;
    }
    __syncthreads();

    int buf = 0;
    for (int kk = 16; kk <= K; kk += 16) {
        uint4 na, nw;
        bool more = (kk < K);
        if (more) {
            na = *(const uint4*)(Ag + kk);
            nw = wv ? *(const uint4*)(Wg + kk) : z4;
        }
        const uint32_t* Ab = As[buf];
        const uint32_t* Bb = Bs[buf];
        uint32_t af[2][4], bf[4][2];
        #pragma unroll
        for (int i = 0; i < 2; i++) {
            uint4 v = *(const uint4*)(Ab + (wm*2 + i)*128 + lane*4);
            af[i][0] = v.x; af[i][1] = v.y; af[i][2] = v.z; af[i][3] = v.w;
        }
        #pragma unroll
        for (int j = 0; j < 4; j++) {
            uint2 v = *(const uint2*)(Bb + (wn*4 + j)*64 + lane*2);
            bf[j][0] = v.x; bf[j][1] = v.y;
        }
        #pragma unroll
        for (int i = 0; i < 2; i++)
            #pragma unroll
            for (int j = 0; j < 4; j++)
                mma16(acc[i][j], af[i], bf[j]);
        if (more) {
            uint32_t* ab = &As[buf^1][aoff];
            ab[0]=na.x; ab[4]=na.y; ab[8]=na.z; ab[12]=na.w;
            uint32_t* bb = &Bs[buf^1][boff];
            bb[0]=nw.x; bb[2]=nw.y; bb[4]=nw.z; bb[6]=nw.w;
            __syncthreads();
            buf ^= 1;
        }
    }

    int r = lane >> 2, c2 = (lane & 3) * 2;
    #pragma unroll
    for (int i = 0; i < 2; i++) {
        int gr = row0 + wm*32 + i*16 + r;
        size_t rb0 = (size_t)gr * N;
        size_t rb1 = (size_t)(gr + 8) * N;
        #pragma unroll
        for (int j = 0; j < 4; j++) {
            int gc = col0 + wn*32 + j*8 + c2;
            const float* cp = acc[i][j];
            if (gc + 1 < N) {
                float b0 = bias[gc], b1 = bias[gc+1];
                float v0 = cp[0] + b0, v1 = cp[1] + b1;
                float v2 = cp[2] + b0, v3 = cp[3] + b1;
                if (epi == 0) {
                    C[rb0 + gc] = v0; C[rb0 + gc + 1] = v1;
                    C[rb1 + gc] = v2; C[rb1 + gc + 1] = v3;
                } else if (epi == 1) {
                    *(__half2*)(Ch + rb0 + gc) = __floats2half2_rn(gelu_f(v0), gelu_f(v1));
                    *(__half2*)(Ch + rb1 + gc) = __floats2half2_rn(gelu_f(v2), gelu_f(v3));
                } else {
                    v0 += res[rb0 + gc]; v1 += res[rb0 + gc + 1];
                    v2 += res[rb1 + gc]; v3 += res[rb1 + gc + 1];
                    C[rb0 + gc] = v0; C[rb0 + gc + 1] = v1;
                    C[rb1 + gc] = v2; C[rb1 + gc + 1] = v3;
                    if (epi == 3) {
                        *(__half2*)(Ch + rb0 + gc) = __floats2half2_rn(v0, v1);
                        *(__half2*)(Ch + rb1 + gc) = __floats2half2_rn(v2, v3);
                    }
                }
            } else if (gc < N) {
                float b0 = bias[gc];
                float v0 = cp[0] + b0, v2 = cp[2] + b0;
                if (epi == 0) {
                    C[rb0 + gc] = v0; C[rb1 + gc] = v2;
                } else if (epi == 1) {
                    Ch[rb0 + gc] = __float2half(gelu_f(v0));
                    Ch[rb1 + gc] = __float2half(gelu_f(v2));
                } else {
                    v0 += res[rb0 + gc]; v2 += res[rb1 + gc];
                    C[rb0 + gc] = v0; C[rb1 + gc] = v2;
                    if (epi == 3) {
                        Ch[rb0 + gc] = __float2half(v0);
                        Ch[rb1 + gc] = __float2half(v2);
                    }
                }
            }
        }
    }
}

// ---------------- attention: grid (H, B, 2) -- ctx written as half ----------------
#define KTP 104

__global__ void __launch_bounds__(512) attn_kernel(
        const float* __restrict__ q, const float* __restrict__ k1,
        const float* __restrict__ k2, const float* __restrict__ v,
        const int* __restrict__ x, const float* __restrict__ ml,
        __half* __restrict__ ctx)
{
    extern __shared__ float sm[];
    float* qs  = sm;                    // SH*64
    float* vs  = qs  + SH*DK_;          // SS*64
    float* kct = vs  + SS*DK_;          // 64*KTP
    float* sc  = kct + DK_*KTP;         // SH*SS
    float* offs= sc + SH*SS;            // SS
    int h = blockIdx.x, b = blockIdx.y, z = blockIdx.z;
    int tid = threadIdx.x;
    int lane = tid & 31, warp = tid >> 5;
    int base = b*SS*DD + h*DK_;
    int q0 = z*SH;

    for (int idx = tid; idx < SS*DK_; idx += 512) {
        int s = idx >> 6, d = idx & 63;
        int gi = base + s*DD + d;
        vs[idx] = v[gi];
        bool kp = x[b*SS + s] > 0;
        float k2v = k2[gi];
        kct[d*KTP + s] = kp ? (k1[gi] + k2v) : k2v;
    }
    for (int idx = tid; idx < SH*DK_; idx += 512) {
        int s = idx >> 6, d = idx & 63;
        qs[idx] = q[base + (q0 + s)*DD + d];
    }
    if (tid < SS) offs[tid] = (x[b*SS + tid] > 0) ? 0.0f : -1e9f;
    __syncthreads();

    const float scale = 0.125f;
    for (int g = tid; g < SH*25; g += 512) {
        int qi = g / 25;
        int kg = (g - qi*25) * 4;
        const float* qp = qs + qi*DK_;
        float4 s1 = make_float4(0.f,0.f,0.f,0.f);
        #pragma unroll 8
        for (int d = 0; d < DK_; d++) {
            float qv = qp[d];
            float4 b1 = *(const float4*)(kct + d*KTP + kg);
            s1.x += qv*b1.x; s1.y += qv*b1.y; s1.z += qv*b1.z; s1.w += qv*b1.w;
        }
        float* sr = sc + qi*SS + kg;
        const float* op = offs + kg;
        sr[0] = s1.x*scale + op[0];
        sr[1] = s1.y*scale + op[1];
        sr[2] = s1.z*scale + op[2];
        sr[3] = s1.w*scale + op[3];
    }
    __syncthreads();

    for (int r = warp; r < SH; r += 16) {
        float* row = sc + r*SS;
        float mx = -1e30f;
        for (int c = lane; c < SS; c += 32) mx = fmaxf(mx, row[c]);
        #pragma unroll
        for (int o = 16; o > 0; o >>= 1) mx = fmaxf(mx, __shfl_xor_sync(0xffffffff, mx, o));
        float sum = 0.f;
        for (int c = lane; c < SS; c += 32) {
            float e = __expf(row[c] - mx);
            row[c] = e; sum += e;
        }
        #pragma unroll
        for (int o = 16; o > 0; o >>= 1) sum += __shfl_xor_sync(0xffffffff, sum, o);
        float inv = 1.0f / sum;
        const float* mlr = ml + (q0 + r)*SS;
        for (int c = lane; c < SS; c += 32) {
            float zz = mlr[c];
            float sg = 1.0f / (1.0f + __expf(-zz));
            row[c] *= inv * sg;
        }
    }
    __syncthreads();

    for (int o = tid; o < SH*16; o += 512) {
        int qi = o >> 4;
        int dg = (o & 15) * 4;
        const float* sr = sc + qi*SS;
        const float* vp = vs + dg;
        float4 a = make_float4(0.f,0.f,0.f,0.f);
        #pragma unroll 4
        for (int k = 0; k < SS; k++) {
            float p = sr[k];
            float4 vv = *(const float4*)(vp + k*DK_);
            a.x += p*vv.x; a.y += p*vv.y; a.z += p*vv.z; a.w += p*vv.w;
        }
        __half2* dst = (__half2*)(ctx + base + (q0 + qi)*DD + dg);
        dst[0] = __floats2half2_rn(a.x, a.y);
        dst[1] = __floats2half2_rn(a.z, a.w);
    }
}

// ---------------- host launcher ----------------
extern "C" void kernel_launch(void* const* d_in, const int* in_sizes, int n_in,
                              void* d_out, int out_size)
{
    (void)in_sizes; (void)n_in; (void)out_size;
    const int*   x         = (const int*)  d_in[0];
    const float* times     = (const float*)d_in[1];
    const float* token_emb = (const float*)d_in[2];
    const float* pos_emb   = (const float*)d_in[3];
    const float* sel_w     = (const float*)d_in[4];
    const float* sel_b     = (const float*)d_in[5];
    const float* time_w    = (const float*)d_in[6];
    const float* time_b    = (const float*)d_in[7];
    const float* per_w     = (const float*)d_in[8];
    const float* per_b     = (const float*)d_in[9];
    const float* Wq        = (const float*)d_in[10];
    const float* Wk        = (const float*)d_in[11];
    const float* Wt        = (const float*)d_in[12];
    const float* Wv        = (const float*)d_in[13];
    const float* Wo        = (const float*)d_in[14];
    const float* bq        = (const float*)d_in[15];
    const float* bk        = (const float*)d_in[16];
    const float* bt        = (const float*)d_in[17];
    const float* bv        = (const float*)d_in[18];
    const float* bo        = (const float*)d_in[19];
    const float* mask_log  = (const float*)d_in[20];
    const float* ln1_a     = (const float*)d_in[21];
    const float* ln1_b     = (const float*)d_in[22];
    const float* ln2_a     = (const float*)d_in[23];
    const float* ln2_b     = (const float*)d_in[24];
    const float* ffn_w1    = (const float*)d_in[25];
    const float* ffn_b1    = (const float*)d_in[26];
    const float* ffn_w2    = (const float*)d_in[27];
    const float* ffn_b2    = (const float*)d_in[28];
    const float* out_w     = (const float*)d_in[29];
    const float* out_b     = (const float*)d_in[30];
    float* out = (float*)d_out;

    float *ph,*pq,*pk1,*pk2,*pv;
    __half *phn,*ptemb,*pctx,*pffn,*phh;
    __half *wq,*wk,*wt,*wv_,*wo,*w1,*w2,*wout;
    cudaGetSymbolAddress((void**)&ph,    g_h);
    cudaGetSymbolAddress((void**)&pq,    g_q);
    cudaGetSymbolAddress((void**)&pk1,   g_k1);
    cudaGetSymbolAddress((void**)&pk2,   g_k2);
    cudaGetSymbolAddress((void**)&pv,    g_v);
    cudaGetSymbolAddress((void**)&phn,   g_hn_h);
    cudaGetSymbolAddress((void**)&ptemb, g_temb_h);
    cudaGetSymbolAddress((void**)&pctx,  g_ctx_h);
    cudaGetSymbolAddress((void**)&pffn,  g_ffn_h);
    cudaGetSymbolAddress((void**)&phh,   g_hh);
    cudaGetSymbolAddress((void**)&wq,    g_Wqh);
    cudaGetSymbolAddress((void**)&wk,    g_Wkh);
    cudaGetSymbolAddress((void**)&wt,    g_Wth);
    cudaGetSymbolAddress((void**)&wv_,   g_Wvh);
    cudaGetSymbolAddress((void**)&wo,    g_Woh);
    cudaGetSymbolAddress((void**)&w1,    g_w1h);
    cudaGetSymbolAddress((void**)&w2,    g_w2h);
    cudaGetSymbolAddress((void**)&wout,  g_outwh);

    const int attn_smem = (SH*DK_ + SS*DK_ + DK_*KTP + SH*SS + SS)*(int)sizeof(float); // ~85.4 KB
    cudaFuncSetAttribute(attn_kernel, cudaFuncAttributeMaxDynamicSharedMemorySize, attn_smem);

    // weight conversion (kernels only -> graph-capturable)
    const int nDD = LL*DD*DD/4, nF = LL*DFF_*DD/4, nOut = NOUT*DD/4;
    f2h_kernel<<<(nDD+255)/256, 256>>>(Wq, wq, nDD);
    f2h_kernel<<<(nDD+255)/256, 256>>>(Wk, wk, nDD);
    f2h_kernel<<<(nDD+255)/256, 256>>>(Wt, wt, nDD);
    f2h_kernel<<<(nDD+255)/256, 256>>>(Wv, wv_, nDD);
    f2h_kernel<<<(nDD+255)/256, 256>>>(Wo, wo, nDD);
    f2h_kernel<<<(nF+255)/256, 256>>>(ffn_w1, w1, nF);
    f2h_kernel<<<(nF+255)/256, 256>>>(ffn_w2, w2, nF);
    f2h_kernel<<<(nOut+255)/256, 256>>>(out_w, wout, nOut);

    embed_kernel<<<MM, 256>>>(x, times, token_emb, pos_emb, sel_w, sel_b,
                              time_w, time_b, per_w, per_b);

    dim3 gF(8, 25);            // 128x128 tiles, N=1024
    dim3 gS(4, 50);            // 64x64 tiles, N=256
    dim3 gQKTV(2, 25, 4);
    for (int l = 0; l < LL; l++) {
        ln_kernel<<<MM, 256>>>(ph, ln1_a + l*DD, ln1_b + l*DD, phn);
        qktv_gemm<<<gQKTV, 256>>>(phn, ptemb,
                                  wq + (size_t)l*DD*DD, wk + (size_t)l*DD*DD,
                                  wt + (size_t)l*DD*DD, wv_ + (size_t)l*DD*DD,
                                  bq + l*DD, bk + l*DD, bt + l*DD, bv + l*DD,
                                  pq, pk1, pk2, pv);
        attn_kernel<<<dim3(HH, BB, 2), 512, attn_smem>>>(pq, pk1, pk2, pv, x,
                                                         mask_log + l*SS*SS, pctx);
        gemm_s<<<gS, 128>>>(pctx, wo + (size_t)l*DD*DD, bo + l*DD, ph, ph, nullptr, DD, DD, 2);
        ln_kernel<<<MM, 256>>>(ph, ln2_a + l*DD, ln2_b + l*DD, phn);
        gemm_mma<<<gF, 256>>>(phn, w1 + (size_t)l*DFF_*DD, ffn_b1 + l*DFF_,
                              nullptr, nullptr, pffn, DFF_, DD, 1);
        gemm_s<<<gS, 128>>>(pffn, w2 + (size_t)l*DD*DFF_, ffn_b2 + l*DD, ph, ph, phh, DD, DFF_, 3);
    }
    gemm_mma<<<dim3(391, 25), 256>>>(phh, wout, out_b, nullptr, out, nullptr, NOUT, DD, 0);
}